// round 1
// baseline (speedup 1.0000x reference)
#include <cuda_runtime.h>
#include <cstdint>

#define N_NODES 10000
#define D_IN    512
#define D_HID   1024

// Scratch (allocation-free rule: __device__ globals)
__device__ float g_rst[N_NODES * D_IN];   // (1+eps)*feat + neighbor sum
__device__ float g_h[N_NODES * D_HID];    // hidden activations

// ---------------------------------------------------------------------------
// Kernel 1: rst = (1+eps) * feat   (vectorized float4)
// ---------------------------------------------------------------------------
__global__ void init_rst_kernel(const float* __restrict__ feat,
                                const float* __restrict__ eps,
                                float* __restrict__ rst, int n4) {
    int i = blockIdx.x * blockDim.x + threadIdx.x;
    if (i >= n4) return;
    float s = 1.0f + eps[0];
    float4 v = reinterpret_cast<const float4*>(feat)[i];
    v.x *= s; v.y *= s; v.z *= s; v.w *= s;
    reinterpret_cast<float4*>(rst)[i] = v;
}

// ---------------------------------------------------------------------------
// Kernel 2: edge scatter — one warp per edge.
// rst[dst[e]] += feat[src[e]]  (512 floats = 128 float4 per edge)
// Uses red.global.add.v4.f32 (no-return reduction, sm_90+).
// ---------------------------------------------------------------------------
__global__ void edge_scatter_kernel(const float* __restrict__ feat,
                                    const int* __restrict__ src,
                                    const int* __restrict__ dst,
                                    float* __restrict__ rst, int n_edges) {
    int warp = (blockIdx.x * blockDim.x + threadIdx.x) >> 5;
    int lane = threadIdx.x & 31;
    if (warp >= n_edges) return;
    int s = src[warp];
    int d = dst[warp];
    const float4* fs = reinterpret_cast<const float4*>(feat + (size_t)s * D_IN);
    float* fd = rst + (size_t)d * D_IN;
#pragma unroll
    for (int i = 0; i < 4; i++) {
        int idx = lane + i * 32;          // float4 index 0..127
        float4 v = fs[idx];
        float* addr = fd + idx * 4;
        asm volatile("red.global.add.v4.f32 [%0], {%1, %2, %3, %4};"
                     :: "l"(addr), "f"(v.x), "f"(v.y), "f"(v.z), "f"(v.w)
                     : "memory");
    }
}

// ---------------------------------------------------------------------------
// Kernel 3/4: tiled SIMT fp32 GEMM  C[M,N] = op(A[M,K] @ B[K,N] + bias [+ resid])
// BM=128, BN=128, BK=16, TM=TN=8, 256 threads.
// RELU: epilogue max(0, .)   RESID: epilogue += resid[M,N]
// ---------------------------------------------------------------------------
template <bool RELU, bool RESID>
__global__ __launch_bounds__(256, 2)
void gemm_kernel(const float* __restrict__ A, const float* __restrict__ B,
                 const float* __restrict__ bias, const float* __restrict__ resid,
                 float* __restrict__ C, int M, int N, int K) {
    constexpr int BM = 128, BN = 128, BK = 16, TM = 8, TN = 8;
    __shared__ float As[BK][BM];
    __shared__ float Bs[BK][BN];

    const int tid = threadIdx.x;
    const int tx = tid & 15;          // 0..15 -> N direction
    const int ty = tid >> 4;          // 0..15 -> M direction
    const int rowBase = blockIdx.y * BM;
    const int colBase = blockIdx.x * BN;

    float acc[TM][TN];
#pragma unroll
    for (int m = 0; m < TM; m++)
#pragma unroll
        for (int n = 0; n < TN; n++) acc[m][n] = 0.0f;

    for (int k0 = 0; k0 < K; k0 += BK) {
        // Load A tile: 128 rows x 16 cols = 512 float4, 2 per thread (transposed store)
#pragma unroll
        for (int i = 0; i < 2; i++) {
            int lin = tid + i * 256;
            int r = lin >> 2;         // row within tile (0..127)
            int c4 = lin & 3;         // which float4 in the 16-wide row
            int grow = rowBase + r;
            float4 v = make_float4(0.f, 0.f, 0.f, 0.f);
            if (grow < M)
                v = *reinterpret_cast<const float4*>(A + (size_t)grow * K + k0 + c4 * 4);
            As[c4 * 4 + 0][r] = v.x;
            As[c4 * 4 + 1][r] = v.y;
            As[c4 * 4 + 2][r] = v.z;
            As[c4 * 4 + 3][r] = v.w;
        }
        // Load B tile: 16 rows x 128 cols = 512 float4, 2 per thread
#pragma unroll
        for (int i = 0; i < 2; i++) {
            int lin = tid + i * 256;
            int r = lin >> 5;         // k row (0..15)
            int c4 = lin & 31;        // float4 within 128-wide row
            float4 v = *reinterpret_cast<const float4*>(
                B + (size_t)(k0 + r) * N + colBase + c4 * 4);
            *reinterpret_cast<float4*>(&Bs[r][c4 * 4]) = v;
        }
        __syncthreads();

#pragma unroll
        for (int k = 0; k < BK; k++) {
            float a[TM], b[TN];
#pragma unroll
            for (int m = 0; m < TM; m++) a[m] = As[k][ty * TM + m];
#pragma unroll
            for (int n = 0; n < TN; n++) b[n] = Bs[k][tx * TN + n];
#pragma unroll
            for (int m = 0; m < TM; m++)
#pragma unroll
                for (int n = 0; n < TN; n++)
                    acc[m][n] = fmaf(a[m], b[n], acc[m][n]);
        }
        __syncthreads();
    }

    // Epilogue
#pragma unroll
    for (int m = 0; m < TM; m++) {
        int grow = rowBase + ty * TM + m;
        if (grow >= M) continue;
#pragma unroll
        for (int n = 0; n < TN; n += 4) {
            int gcol = colBase + tx * TN + n;
            float4 v;
            v.x = acc[m][n + 0] + bias[gcol + 0];
            v.y = acc[m][n + 1] + bias[gcol + 1];
            v.z = acc[m][n + 2] + bias[gcol + 2];
            v.w = acc[m][n + 3] + bias[gcol + 3];
            if (RELU) {
                v.x = fmaxf(v.x, 0.f); v.y = fmaxf(v.y, 0.f);
                v.z = fmaxf(v.z, 0.f); v.w = fmaxf(v.w, 0.f);
            }
            if (RESID) {
                float4 r = *reinterpret_cast<const float4*>(
                    resid + (size_t)grow * N + gcol);
                v.x += r.x; v.y += r.y; v.z += r.z; v.w += r.w;
            }
            *reinterpret_cast<float4*>(C + (size_t)grow * N + gcol) = v;
        }
    }
}

// ---------------------------------------------------------------------------
extern "C" void kernel_launch(void* const* d_in, const int* in_sizes, int n_in,
                              void* d_out, int out_size) {
    const float* feat = (const float*)d_in[0];
    const float* W1   = (const float*)d_in[1];
    const float* b1   = (const float*)d_in[2];
    const float* W2   = (const float*)d_in[3];
    const float* b2   = (const float*)d_in[4];
    const float* eps  = (const float*)d_in[5];
    const int*   src  = (const int*)d_in[6];
    const int*   dst  = (const int*)d_in[7];
    const int n_edges = in_sizes[6];
    float* out = (float*)d_out;

    float* rst = nullptr;
    float* h   = nullptr;
    cudaGetSymbolAddress((void**)&rst, g_rst);
    cudaGetSymbolAddress((void**)&h, g_h);

    // 1) rst = (1+eps) * feat
    {
        int n4 = N_NODES * D_IN / 4;
        init_rst_kernel<<<(n4 + 255) / 256, 256>>>(feat, eps, rst, n4);
    }
    // 2) scatter-add neighbor features (one warp per edge)
    {
        int warps_per_block = 256 / 32;
        int blocks = (n_edges + warps_per_block - 1) / warps_per_block;
        edge_scatter_kernel<<<blocks, 256>>>(feat, src, dst, rst, n_edges);
    }
    // 3) h = relu(rst @ W1 + b1)   [10000,512] @ [512,1024]
    {
        dim3 grid(D_HID / 128, (N_NODES + 127) / 128);
        gemm_kernel<true, false><<<grid, 256>>>(rst, W1, b1, nullptr, h,
                                                N_NODES, D_HID, D_IN);
    }
    // 4) out = h @ W2 + b2 + feat  [10000,1024] @ [1024,512]
    {
        dim3 grid(D_IN / 128, (N_NODES + 127) / 128);
        gemm_kernel<false, true><<<grid, 256>>>(h, W2, b2, feat, out,
                                                N_NODES, D_IN, D_HID);
    }
}

// round 2
// speedup vs baseline: 2.3960x; 2.3960x over previous
#include <cuda_runtime.h>
#include <cstdint>

#define N_NODES 10000
#define D_IN    512
#define D_HID   1024

// Scratch (allocation-free rule: __device__ globals)
__device__ float g_rst[N_NODES * D_IN];   // (1+eps)*feat + neighbor sum
__device__ float g_h[N_NODES * D_HID];    // hidden activations

// ---------------------------------------------------------------------------
// Kernel 1: rst = (1+eps) * feat   (vectorized float4)
// ---------------------------------------------------------------------------
__global__ void init_rst_kernel(const float* __restrict__ feat,
                                const float* __restrict__ eps,
                                float* __restrict__ rst, int n4) {
    int i = blockIdx.x * blockDim.x + threadIdx.x;
    if (i >= n4) return;
    float s = 1.0f + eps[0];
    float4 v = reinterpret_cast<const float4*>(feat)[i];
    v.x *= s; v.y *= s; v.z *= s; v.w *= s;
    reinterpret_cast<float4*>(rst)[i] = v;
}

// ---------------------------------------------------------------------------
// Kernel 2: edge scatter — one warp per edge.
// rst[dst[e]] += feat[src[e]]  (512 floats = 128 float4 per edge)
// ---------------------------------------------------------------------------
__global__ void edge_scatter_kernel(const float* __restrict__ feat,
                                    const int* __restrict__ src,
                                    const int* __restrict__ dst,
                                    float* __restrict__ rst, int n_edges) {
    int warp = (blockIdx.x * blockDim.x + threadIdx.x) >> 5;
    int lane = threadIdx.x & 31;
    if (warp >= n_edges) return;
    int s = src[warp];
    int d = dst[warp];
    const float4* fs = reinterpret_cast<const float4*>(feat + (size_t)s * D_IN);
    float* fd = rst + (size_t)d * D_IN;
#pragma unroll
    for (int i = 0; i < 4; i++) {
        int idx = lane + i * 32;          // float4 index 0..127
        float4 v = fs[idx];
        float* addr = fd + idx * 4;
        asm volatile("red.global.add.v4.f32 [%0], {%1, %2, %3, %4};"
                     :: "l"(addr), "f"(v.x), "f"(v.y), "f"(v.z), "f"(v.w)
                     : "memory");
    }
}

// ---------------------------------------------------------------------------
// TF32 tensor-core GEMM:  C[M,N] = op(A[M,K] @ B[K,N] + bias [+ resid])
// CTA tile 128x128, BK=32, 8 warps as 2(M)x4(N) -> 64x32 warp tiles.
// mma.sync.aligned.m16n8k8.row.col.f32.tf32.tf32.f32
// ---------------------------------------------------------------------------
__device__ __forceinline__ uint32_t f32_to_tf32(float f) {
    uint32_t r;
    asm("cvt.rna.tf32.f32 %0, %1;" : "=r"(r) : "f"(f));
    return r;
}

template <bool RELU, bool RESID>
__global__ __launch_bounds__(256)
void gemm_tf32_kernel(const float* __restrict__ A, const float* __restrict__ B,
                      const float* __restrict__ bias, const float* __restrict__ resid,
                      float* __restrict__ C, int M, int N, int K) {
    constexpr int BM = 128, BN = 128, BK = 32;
    constexpr int ASTR = BK + 4;      // 36 words: A-frag LDS bank = (4*qr+qc)&31, conflict-free
    constexpr int BSTR = BN + 8;      // 136 words: B-frag LDS bank = (8*qc+qr)&31, conflict-free

    __shared__ uint32_t As[BM][ASTR];
    __shared__ uint32_t Bs[BK][BSTR];

    const int tid  = threadIdx.x;
    const int lane = tid & 31;
    const int wid  = tid >> 5;
    const int wm   = wid >> 2;        // 0..1  (M direction)
    const int wn   = wid & 3;         // 0..3  (N direction)
    const int qr   = lane >> 2;       // 0..7
    const int qc   = lane & 3;        // 0..3

    const int rowBase = blockIdx.y * BM;
    const int colBase = blockIdx.x * BN;

    // accumulators: 4 m-frags x 4 n-frags x 4 regs
    float acc[4][4][4];
#pragma unroll
    for (int mf = 0; mf < 4; mf++)
#pragma unroll
        for (int nf = 0; nf < 4; nf++)
#pragma unroll
            for (int r = 0; r < 4; r++) acc[mf][nf][r] = 0.0f;

    for (int k0 = 0; k0 < K; k0 += BK) {
        // ---- load A tile: 128 rows x 32 cols = 1024 float4, 4 per thread ----
#pragma unroll
        for (int i = 0; i < 4; i++) {
            int lin = tid + i * 256;
            int r   = lin >> 3;       // 0..127
            int c4  = lin & 7;        // 0..7
            int grow = rowBase + r;
            float4 v = make_float4(0.f, 0.f, 0.f, 0.f);
            if (grow < M)
                v = *reinterpret_cast<const float4*>(A + (size_t)grow * K + k0 + c4 * 4);
            uint4 t;
            t.x = f32_to_tf32(v.x); t.y = f32_to_tf32(v.y);
            t.z = f32_to_tf32(v.z); t.w = f32_to_tf32(v.w);
            *reinterpret_cast<uint4*>(&As[r][c4 * 4]) = t;
        }
        // ---- load B tile: 32 rows x 128 cols = 1024 float4, 4 per thread ----
#pragma unroll
        for (int i = 0; i < 4; i++) {
            int lin = tid + i * 256;
            int r   = lin >> 5;       // 0..31
            int c4  = lin & 31;       // 0..31
            float4 v = *reinterpret_cast<const float4*>(
                B + (size_t)(k0 + r) * N + colBase + c4 * 4);
            uint4 t;
            t.x = f32_to_tf32(v.x); t.y = f32_to_tf32(v.y);
            t.z = f32_to_tf32(v.z); t.w = f32_to_tf32(v.w);
            *reinterpret_cast<uint4*>(&Bs[r][c4 * 4]) = t;
        }
        __syncthreads();

        // ---- compute: 4 k-steps of 8 ----
#pragma unroll
        for (int ks = 0; ks < 4; ks++) {
            uint32_t a[4][4];
#pragma unroll
            for (int mf = 0; mf < 4; mf++) {
                int mrow = wm * 64 + mf * 16 + qr;
                a[mf][0] = As[mrow    ][ks * 8 + qc    ];
                a[mf][1] = As[mrow + 8][ks * 8 + qc    ];
                a[mf][2] = As[mrow    ][ks * 8 + qc + 4];
                a[mf][3] = As[mrow + 8][ks * 8 + qc + 4];
            }
            uint32_t b[4][2];
#pragma unroll
            for (int nf = 0; nf < 4; nf++) {
                int ncol = wn * 32 + nf * 8 + qr;
                b[nf][0] = Bs[ks * 8 + qc    ][ncol];
                b[nf][1] = Bs[ks * 8 + qc + 4][ncol];
            }
#pragma unroll
            for (int mf = 0; mf < 4; mf++)
#pragma unroll
                for (int nf = 0; nf < 4; nf++) {
                    asm volatile(
                        "mma.sync.aligned.m16n8k8.row.col.f32.tf32.tf32.f32 "
                        "{%0,%1,%2,%3}, {%4,%5,%6,%7}, {%8,%9}, {%0,%1,%2,%3};"
                        : "+f"(acc[mf][nf][0]), "+f"(acc[mf][nf][1]),
                          "+f"(acc[mf][nf][2]), "+f"(acc[mf][nf][3])
                        : "r"(a[mf][0]), "r"(a[mf][1]), "r"(a[mf][2]), "r"(a[mf][3]),
                          "r"(b[nf][0]), "r"(b[nf][1]));
                }
        }
        __syncthreads();
    }

    // ---- epilogue: C frag layout c0,c1 at (qr, 2qc+{0,1}); c2,c3 at (qr+8, .) ----
#pragma unroll
    for (int mf = 0; mf < 4; mf++) {
#pragma unroll
        for (int half = 0; half < 2; half++) {
            int grow = rowBase + wm * 64 + mf * 16 + qr + half * 8;
            if (grow >= M) continue;
#pragma unroll
            for (int nf = 0; nf < 4; nf++) {
                int gcol = colBase + wn * 32 + nf * 8 + 2 * qc;
                float2 v;
                v.x = acc[mf][nf][half * 2 + 0] + bias[gcol + 0];
                v.y = acc[mf][nf][half * 2 + 1] + bias[gcol + 1];
                if (RELU) { v.x = fmaxf(v.x, 0.f); v.y = fmaxf(v.y, 0.f); }
                if (RESID) {
                    float2 r = *reinterpret_cast<const float2*>(
                        resid + (size_t)grow * N + gcol);
                    v.x += r.x; v.y += r.y;
                }
                *reinterpret_cast<float2*>(C + (size_t)grow * N + gcol) = v;
            }
        }
    }
}

// ---------------------------------------------------------------------------
extern "C" void kernel_launch(void* const* d_in, const int* in_sizes, int n_in,
                              void* d_out, int out_size) {
    const float* feat = (const float*)d_in[0];
    const float* W1   = (const float*)d_in[1];
    const float* b1   = (const float*)d_in[2];
    const float* W2   = (const float*)d_in[3];
    const float* b2   = (const float*)d_in[4];
    const float* eps  = (const float*)d_in[5];
    const int*   src  = (const int*)d_in[6];
    const int*   dst  = (const int*)d_in[7];
    const int n_edges = in_sizes[6];
    float* out = (float*)d_out;

    float* rst = nullptr;
    float* h   = nullptr;
    cudaGetSymbolAddress((void**)&rst, g_rst);
    cudaGetSymbolAddress((void**)&h, g_h);

    // 1) rst = (1+eps) * feat
    {
        int n4 = N_NODES * D_IN / 4;
        init_rst_kernel<<<(n4 + 255) / 256, 256>>>(feat, eps, rst, n4);
    }
    // 2) scatter-add neighbor features (one warp per edge)
    {
        int warps_per_block = 256 / 32;
        int blocks = (n_edges + warps_per_block - 1) / warps_per_block;
        edge_scatter_kernel<<<blocks, 256>>>(feat, src, dst, rst, n_edges);
    }
    // 3) h = relu(rst @ W1 + b1)   [10000,512] @ [512,1024]
    {
        dim3 grid(D_HID / 128, (N_NODES + 127) / 128);
        gemm_tf32_kernel<true, false><<<grid, 256>>>(rst, W1, b1, nullptr, h,
                                                     N_NODES, D_HID, D_IN);
    }
    // 4) out = h @ W2 + b2 + feat  [10000,1024] @ [1024,512]
    {
        dim3 grid(D_IN / 128, (N_NODES + 127) / 128);
        gemm_tf32_kernel<false, true><<<grid, 256>>>(h, W2, b2, feat, out,
                                                     N_NODES, D_IN, D_HID);
    }
}

// round 4
// speedup vs baseline: 2.5383x; 1.0594x over previous
#include <cuda_runtime.h>
#include <cstdint>

#define N_NODES 10000
#define D_IN    512
#define D_HID   1024

// ---------------- scratch (__device__ globals; no allocs) ------------------
__device__ float    g_rst[N_NODES * D_IN];     // (1+eps)*feat + neighbor sum (f32)
__device__ uint32_t g_rst_t[N_NODES * D_IN];   // rst as tf32
__device__ uint32_t g_h[N_NODES * D_HID];      // hidden activations as tf32
__device__ uint32_t g_w1t[D_IN * D_HID];       // W1 as tf32 [K=512, N=1024]
__device__ uint32_t g_w2t[D_HID * D_IN];       // W2 as tf32 [K=1024, N=512]

// ---------------- helpers --------------------------------------------------
__device__ __forceinline__ uint32_t f32_to_tf32(float f) {
    uint32_t r;
    asm("cvt.rna.tf32.f32 %0, %1;" : "=r"(r) : "f"(f));
    return r;
}
__device__ __forceinline__ uint32_t smem_u32(const void* p) {
    uint32_t a;
    asm("{ .reg .u64 t; cvta.to.shared.u64 t, %1; cvt.u32.u64 %0, t; }"
        : "=r"(a) : "l"(p));
    return a;
}
__device__ __forceinline__ void cp_async16(uint32_t dst, const void* src, uint32_t bytes) {
    asm volatile("cp.async.ca.shared.global [%0], [%1], 16, %2;"
                 :: "r"(dst), "l"(src), "r"(bytes) : "memory");
}
#define CP_COMMIT() asm volatile("cp.async.commit_group;" ::: "memory")
#define CP_WAIT1()  asm volatile("cp.async.wait_group 1;" ::: "memory")

// ---------------------------------------------------------------------------
// rst = (1+eps) * feat
// ---------------------------------------------------------------------------
__global__ void init_rst_kernel(const float* __restrict__ feat,
                                const float* __restrict__ eps,
                                float* __restrict__ rst, int n4) {
    int i = blockIdx.x * blockDim.x + threadIdx.x;
    if (i >= n4) return;
    float s = 1.0f + eps[0];
    float4 v = reinterpret_cast<const float4*>(feat)[i];
    v.x *= s; v.y *= s; v.z *= s; v.w *= s;
    reinterpret_cast<float4*>(rst)[i] = v;
}

// ---------------------------------------------------------------------------
// edge scatter: one warp per edge, red.global.add.v4.f32
// ---------------------------------------------------------------------------
__global__ void edge_scatter_kernel(const float* __restrict__ feat,
                                    const int* __restrict__ src,
                                    const int* __restrict__ dst,
                                    float* __restrict__ rst, int n_edges) {
    int warp = (blockIdx.x * blockDim.x + threadIdx.x) >> 5;
    int lane = threadIdx.x & 31;
    if (warp >= n_edges) return;
    int s = src[warp];
    int d = dst[warp];
    const float4* fs = reinterpret_cast<const float4*>(feat + (size_t)s * D_IN);
    float* fd = rst + (size_t)d * D_IN;
#pragma unroll
    for (int i = 0; i < 4; i++) {
        int idx = lane + i * 32;
        float4 v = fs[idx];
        float* addr = fd + idx * 4;
        asm volatile("red.global.add.v4.f32 [%0], {%1, %2, %3, %4};"
                     :: "l"(addr), "f"(v.x), "f"(v.y), "f"(v.z), "f"(v.w)
                     : "memory");
    }
}

// ---------------------------------------------------------------------------
// elementwise f32 -> tf32
// ---------------------------------------------------------------------------
__global__ void cvt_tf32_kernel(const float* __restrict__ in,
                                uint32_t* __restrict__ out, int n4) {
    int i = blockIdx.x * blockDim.x + threadIdx.x;
    if (i >= n4) return;
    float4 v = reinterpret_cast<const float4*>(in)[i];
    uint4 t;
    t.x = f32_to_tf32(v.x); t.y = f32_to_tf32(v.y);
    t.z = f32_to_tf32(v.z); t.w = f32_to_tf32(v.w);
    reinterpret_cast<uint4*>(out)[i] = t;
}

// ---------------------------------------------------------------------------
// TF32 mma.sync GEMM with 3-stage cp.async pipeline.
//   C[M,N] = op(A[M,K] @ B[K,N] + bias [+ resid])
// A, B already tf32 (uint32). CTA tile 128x128, BK=32, 8 warps as 2(M)x4(N).
// Smem per stage: A 128x36 words (18432 B) + B 32x136 words (17408 B).
// OUT_TF32: store cvt.rna.tf32 results as uint32 (feeds next GEMM).
// ---------------------------------------------------------------------------
#define ASTR 36
#define BSTR 136
#define A_BYTES (128 * ASTR * 4)         // 18432
#define STAGE_BYTES (A_BYTES + 32 * BSTR * 4)  // 18432 + 17408 = 35840
#define NSTAGE 3
#define GSM_TOTAL (NSTAGE * STAGE_BYTES)

template <bool RELU, bool RESID, bool OUT_TF32>
__global__ __launch_bounds__(256, 2)
void gemm_async_kernel(const uint32_t* __restrict__ A, const uint32_t* __restrict__ B,
                       const float* __restrict__ bias, const float* __restrict__ resid,
                       float* __restrict__ Cf, uint32_t* __restrict__ Ct,
                       int M, int N, int K) {
    extern __shared__ char sm[];
    const uint32_t sbase = smem_u32(sm);
    const int tid  = threadIdx.x;
    const int lane = tid & 31;
    const int wid  = tid >> 5;
    const int wm   = wid >> 2;        // 0..1 (M)
    const int wn   = wid & 3;         // 0..3 (N)
    const int qr   = lane >> 2;       // 0..7
    const int qc   = lane & 3;        // 0..3

    const int rowBase = blockIdx.y * 128;
    const int colBase = blockIdx.x * 128;
    const int NC = K >> 5;

    // per-thread load coords
    const int ar  = tid >> 3;         // base row step: lin = tid + i*256 -> r = lin>>3
    const int ac4 = tid & 7;
    const int br  = tid >> 5;         // lin>>5
    const int bc4 = tid & 31;

    float acc[4][4][4];
#pragma unroll
    for (int mf = 0; mf < 4; mf++)
#pragma unroll
        for (int nf = 0; nf < 4; nf++)
#pragma unroll
            for (int r = 0; r < 4; r++) acc[mf][nf][r] = 0.0f;

    // ---- stage loader ----
    auto load_stage = [&](int slot, int chunk) {
        const uint32_t abase = sbase + slot * STAGE_BYTES;
        const uint32_t bbase = abase + A_BYTES;
        const int k0 = chunk * 32;
        // A: 128 rows x 32 words = 1024 chunks of 16B, 4 per thread
#pragma unroll
        for (int i = 0; i < 4; i++) {
            int r  = ar + i * 32;     // (tid + i*256) >> 3
            int grow = rowBase + r;
            uint32_t dst = abase + (r * ASTR + ac4 * 4) * 4;
            const uint32_t* src = A + (size_t)grow * K + k0 + ac4 * 4;
            cp_async16(dst, src, (grow < M) ? 16u : 0u);
        }
        // B: 32 rows x 128 words = 1024 chunks of 16B, 4 per thread
#pragma unroll
        for (int i = 0; i < 4; i++) {
            int r = br + i * 8;       // (tid + i*256) >> 5
            uint32_t dst = bbase + (r * BSTR + bc4 * 4) * 4;
            const uint32_t* src = B + (size_t)(k0 + r) * N + colBase + bc4 * 4;
            cp_async16(dst, src, 16u);
        }
        CP_COMMIT();
    };

    // prologue: stages 0,1
    load_stage(0, 0);
    if (NC > 1) load_stage(1, 1);

    for (int ci = 0; ci < NC; ci++) {
        CP_WAIT1();
        __syncthreads();

        int nci = ci + 2;
        if (nci < NC) load_stage(nci % NSTAGE, nci);

        const int slot = ci % NSTAGE;
        const uint32_t* As = reinterpret_cast<const uint32_t*>(sm + slot * STAGE_BYTES);
        const uint32_t* Bs = reinterpret_cast<const uint32_t*>(sm + slot * STAGE_BYTES + A_BYTES);

#pragma unroll
        for (int ks = 0; ks < 4; ks++) {
            uint32_t a[4][4];
#pragma unroll
            for (int mf = 0; mf < 4; mf++) {
                int mrow = wm * 64 + mf * 16 + qr;
                a[mf][0] = As[(mrow    ) * ASTR + ks * 8 + qc    ];
                a[mf][1] = As[(mrow + 8) * ASTR + ks * 8 + qc    ];
                a[mf][2] = As[(mrow    ) * ASTR + ks * 8 + qc + 4];
                a[mf][3] = As[(mrow + 8) * ASTR + ks * 8 + qc + 4];
            }
            uint32_t b[4][2];
#pragma unroll
            for (int nf = 0; nf < 4; nf++) {
                int ncol = wn * 32 + nf * 8 + qr;
                b[nf][0] = Bs[(ks * 8 + qc    ) * BSTR + ncol];
                b[nf][1] = Bs[(ks * 8 + qc + 4) * BSTR + ncol];
            }
#pragma unroll
            for (int mf = 0; mf < 4; mf++)
#pragma unroll
                for (int nf = 0; nf < 4; nf++) {
                    asm volatile(
                        "mma.sync.aligned.m16n8k8.row.col.f32.tf32.tf32.f32 "
                        "{%0,%1,%2,%3}, {%4,%5,%6,%7}, {%8,%9}, {%0,%1,%2,%3};"
                        : "+f"(acc[mf][nf][0]), "+f"(acc[mf][nf][1]),
                          "+f"(acc[mf][nf][2]), "+f"(acc[mf][nf][3])
                        : "r"(a[mf][0]), "r"(a[mf][1]), "r"(a[mf][2]), "r"(a[mf][3]),
                          "r"(b[nf][0]), "r"(b[nf][1]));
                }
        }
        __syncthreads();
    }

    // ---- epilogue: c0,c1 at (qr, 2qc+{0,1}); c2,c3 at (qr+8, .) ----
#pragma unroll
    for (int mf = 0; mf < 4; mf++) {
#pragma unroll
        for (int half = 0; half < 2; half++) {
            int grow = rowBase + wm * 64 + mf * 16 + qr + half * 8;
            if (grow >= M) continue;
#pragma unroll
            for (int nf = 0; nf < 4; nf++) {
                int gcol = colBase + wn * 32 + nf * 8 + 2 * qc;
                float x = acc[mf][nf][half * 2 + 0] + bias[gcol + 0];
                float y = acc[mf][nf][half * 2 + 1] + bias[gcol + 1];
                if (RELU) { x = fmaxf(x, 0.f); y = fmaxf(y, 0.f); }
                if (RESID) {
                    float2 r = *reinterpret_cast<const float2*>(
                        resid + (size_t)grow * N + gcol);
                    x += r.x; y += r.y;
                }
                if (OUT_TF32) {
                    uint2 t;
                    t.x = f32_to_tf32(x); t.y = f32_to_tf32(y);
                    *reinterpret_cast<uint2*>(Ct + (size_t)grow * N + gcol) = t;
                } else {
                    float2 v; v.x = x; v.y = y;
                    *reinterpret_cast<float2*>(Cf + (size_t)grow * N + gcol) = v;
                }
            }
        }
    }
}

// ---------------------------------------------------------------------------
extern "C" void kernel_launch(void* const* d_in, const int* in_sizes, int n_in,
                              void* d_out, int out_size) {
    const float* feat = (const float*)d_in[0];
    const float* W1   = (const float*)d_in[1];
    const float* b1   = (const float*)d_in[2];
    const float* W2   = (const float*)d_in[3];
    const float* b2   = (const float*)d_in[4];
    const float* eps  = (const float*)d_in[5];
    const int*   src  = (const int*)d_in[6];
    const int*   dst  = (const int*)d_in[7];
    const int n_edges = in_sizes[6];
    float* out = (float*)d_out;

    float*    rst  = nullptr;
    uint32_t* rstt = nullptr;
    uint32_t* h    = nullptr;
    uint32_t* w1t  = nullptr;
    uint32_t* w2t  = nullptr;
    cudaGetSymbolAddress((void**)&rst, g_rst);
    cudaGetSymbolAddress((void**)&rstt, g_rst_t);
    cudaGetSymbolAddress((void**)&h, g_h);
    cudaGetSymbolAddress((void**)&w1t, g_w1t);
    cudaGetSymbolAddress((void**)&w2t, g_w2t);

    cudaFuncSetAttribute(gemm_async_kernel<true, false, true>,
                         cudaFuncAttributeMaxDynamicSharedMemorySize, GSM_TOTAL);
    cudaFuncSetAttribute(gemm_async_kernel<false, true, false>,
                         cudaFuncAttributeMaxDynamicSharedMemorySize, GSM_TOTAL);

    // 0) weights -> tf32 (layout unchanged [K,N])
    {
        int n4 = D_IN * D_HID / 4;
        cvt_tf32_kernel<<<(n4 + 255) / 256, 256>>>(W1, w1t, n4);
        cvt_tf32_kernel<<<(n4 + 255) / 256, 256>>>(W2, w2t, n4);
    }
    // 1) rst = (1+eps) * feat
    {
        int n4 = N_NODES * D_IN / 4;
        init_rst_kernel<<<(n4 + 255) / 256, 256>>>(feat, eps, rst, n4);
    }
    // 2) scatter-add neighbor features
    {
        int blocks = (n_edges + 7) / 8;
        edge_scatter_kernel<<<blocks, 256>>>(feat, src, dst, rst, n_edges);
    }
    // 2b) rst -> tf32
    {
        int n4 = N_NODES * D_IN / 4;
        cvt_tf32_kernel<<<(n4 + 255) / 256, 256>>>(rst, rstt, n4);
    }
    // 3) h = tf32(relu(rst @ W1 + b1))
    {
        dim3 grid(D_HID / 128, (N_NODES + 127) / 128);
        gemm_async_kernel<true, false, true><<<grid, 256, GSM_TOTAL>>>(
            rstt, w1t, b1, nullptr, nullptr, h, N_NODES, D_HID, D_IN);
    }
    // 4) out = h @ W2 + b2 + feat
    {
        dim3 grid(D_IN / 128, (N_NODES + 127) / 128);
        gemm_async_kernel<false, true, false><<<grid, 256, GSM_TOTAL>>>(
            h, w2t, b2, feat, out, nullptr, N_NODES, D_IN, D_HID);
    }
}

// round 6
// speedup vs baseline: 2.7281x; 1.0747x over previous
#include <cuda_runtime.h>
#include <cstdint>

#define N_NODES 10000
#define N_EDGES_MAX 160000
#define D_IN    512
#define D_HID   1024

// ---------------- scratch (__device__ globals; no allocs) ------------------
__device__ uint32_t g_rst_t[N_NODES * D_IN];   // (1+eps)*feat + neigh sum, tf32
__device__ uint32_t g_h[N_NODES * D_HID];      // hidden activations as tf32
__device__ uint32_t g_w1t[D_IN * D_HID];       // W1 as tf32 [K=512, N=1024]
__device__ uint32_t g_w2t[D_HID * D_IN];       // W2 as tf32 [K=1024, N=512]
__device__ int      g_cnt[N_NODES];            // in-degree
__device__ int      g_off[N_NODES];            // CSR start offsets (exclusive scan)
__device__ int      g_cur[N_NODES];            // fill cursors
__device__ int      g_eidx[N_EDGES_MAX];       // src node per CSR slot

// ---------------- helpers --------------------------------------------------
__device__ __forceinline__ uint32_t f32_to_tf32(float f) {
    uint32_t r;
    asm("cvt.rna.tf32.f32 %0, %1;" : "=r"(r) : "f"(f));
    return r;
}
__device__ __forceinline__ uint32_t smem_u32(const void* p) {
    uint32_t a;
    asm("{ .reg .u64 t; cvta.to.shared.u64 t, %1; cvt.u32.u64 %0, t; }"
        : "=r"(a) : "l"(p));
    return a;
}
__device__ __forceinline__ void cp_async16(uint32_t dst, const void* src, uint32_t bytes) {
    asm volatile("cp.async.ca.shared.global [%0], [%1], 16, %2;"
                 :: "r"(dst), "l"(src), "r"(bytes) : "memory");
}
#define CP_COMMIT() asm volatile("cp.async.commit_group;" ::: "memory")
#define CP_WAIT1()  asm volatile("cp.async.wait_group 1;" ::: "memory")

// ---------------------------------------------------------------------------
// CSR build: zero counts -> histogram -> single-block scan -> fill
// ---------------------------------------------------------------------------
__global__ void zero_cnt_kernel(int* __restrict__ cnt, int n) {
    int i = blockIdx.x * blockDim.x + threadIdx.x;
    if (i < n) cnt[i] = 0;
}
__global__ void hist_kernel(const int* __restrict__ dst, int* __restrict__ cnt,
                            int n_edges) {
    int i = blockIdx.x * blockDim.x + threadIdx.x;
    if (i < n_edges) atomicAdd(&cnt[dst[i]], 1);
}
__global__ __launch_bounds__(1024)
void scan_kernel(const int* __restrict__ cnt, int* __restrict__ off,
                 int* __restrict__ cur, int n) {
    __shared__ int buf[1024];
    __shared__ int carry;
    int tid = threadIdx.x;
    if (tid == 0) carry = 0;
    __syncthreads();
    for (int base = 0; base < n; base += 1024) {
        int v = (base + tid < n) ? cnt[base + tid] : 0;
        buf[tid] = v;
        __syncthreads();
#pragma unroll
        for (int s = 1; s < 1024; s <<= 1) {
            int t = (tid >= s) ? buf[tid - s] : 0;
            __syncthreads();
            buf[tid] += t;
            __syncthreads();
        }
        int incl = buf[tid];
        int c = carry;
        int tot = buf[1023];
        __syncthreads();
        if (base + tid < n) {
            int e = c + incl - v;      // exclusive
            off[base + tid] = e;
            cur[base + tid] = e;
        }
        if (tid == 0) carry = c + tot;
        __syncthreads();
    }
}
__global__ void fill_kernel(const int* __restrict__ src, const int* __restrict__ dst,
                            int* __restrict__ cur, int* __restrict__ eidx,
                            int n_edges) {
    int i = blockIdx.x * blockDim.x + threadIdx.x;
    if (i >= n_edges) return;
    int pos = atomicAdd(&cur[dst[i]], 1);
    eidx[pos] = src[i];
}

// ---------------------------------------------------------------------------
// Fused gather: one warp per dst node.
// rstt[d] = tf32( (1+eps)*feat[d] + sum_{s in N(d)} feat[s] )
// ---------------------------------------------------------------------------
__global__ __launch_bounds__(256)
void gather_kernel(const float* __restrict__ feat, const float* __restrict__ eps,
                   const int* __restrict__ off, const int* __restrict__ cnt,
                   const int* __restrict__ eidx, uint32_t* __restrict__ rstt) {
    int warp = (blockIdx.x * blockDim.x + threadIdx.x) >> 5;
    int lane = threadIdx.x & 31;
    if (warp >= N_NODES) return;

    float acc[16];
    // self term
    {
        float s = 1.0f + eps[0];
        const float4* fd = reinterpret_cast<const float4*>(feat + (size_t)warp * D_IN);
#pragma unroll
        for (int i = 0; i < 4; i++) {
            float4 v = fd[lane + i * 32];
            acc[i * 4 + 0] = s * v.x; acc[i * 4 + 1] = s * v.y;
            acc[i * 4 + 2] = s * v.z; acc[i * 4 + 3] = s * v.w;
        }
    }
    int beg = off[warp];
    int deg = cnt[warp];
    for (int j = 0; j < deg; j++) {
        int s = eidx[beg + j];
        const float4* fs = reinterpret_cast<const float4*>(feat + (size_t)s * D_IN);
#pragma unroll
        for (int i = 0; i < 4; i++) {
            float4 v = fs[lane + i * 32];
            acc[i * 4 + 0] += v.x; acc[i * 4 + 1] += v.y;
            acc[i * 4 + 2] += v.z; acc[i * 4 + 3] += v.w;
        }
    }
    uint32_t* ro = rstt + (size_t)warp * D_IN;
#pragma unroll
    for (int i = 0; i < 4; i++) {
        uint4 t;
        t.x = f32_to_tf32(acc[i * 4 + 0]); t.y = f32_to_tf32(acc[i * 4 + 1]);
        t.z = f32_to_tf32(acc[i * 4 + 2]); t.w = f32_to_tf32(acc[i * 4 + 3]);
        reinterpret_cast<uint4*>(ro)[lane + i * 32] = t;
    }
}

// ---------------------------------------------------------------------------
// elementwise f32 -> tf32 (weights)
// ---------------------------------------------------------------------------
__global__ void cvt_tf32_kernel(const float* __restrict__ in,
                                uint32_t* __restrict__ out, int n4) {
    int i = blockIdx.x * blockDim.x + threadIdx.x;
    if (i >= n4) return;
    float4 v = reinterpret_cast<const float4*>(in)[i];
    uint4 t;
    t.x = f32_to_tf32(v.x); t.y = f32_to_tf32(v.y);
    t.z = f32_to_tf32(v.z); t.w = f32_to_tf32(v.w);
    reinterpret_cast<uint4*>(out)[i] = t;
}

// ---------------------------------------------------------------------------
// TF32 mma.sync GEMM with 3-stage cp.async pipeline (unchanged from R4).
// ---------------------------------------------------------------------------
#define ASTR 36
#define BSTR 136
#define A_BYTES (128 * ASTR * 4)
#define STAGE_BYTES (A_BYTES + 32 * BSTR * 4)
#define NSTAGE 3
#define GSM_TOTAL (NSTAGE * STAGE_BYTES)

template <bool RELU, bool RESID, bool OUT_TF32>
__global__ __launch_bounds__(256, 2)
void gemm_async_kernel(const uint32_t* __restrict__ A, const uint32_t* __restrict__ B,
                       const float* __restrict__ bias, const float* __restrict__ resid,
                       float* __restrict__ Cf, uint32_t* __restrict__ Ct,
                       int M, int N, int K) {
    extern __shared__ char sm[];
    const uint32_t sbase = smem_u32(sm);
    const int tid  = threadIdx.x;
    const int lane = tid & 31;
    const int wid  = tid >> 5;
    const int wm   = wid >> 2;
    const int wn   = wid & 3;
    const int qr   = lane >> 2;
    const int qc   = lane & 3;

    const int rowBase = blockIdx.y * 128;
    const int colBase = blockIdx.x * 128;
    const int NC = K >> 5;

    const int ar  = tid >> 3;
    const int ac4 = tid & 7;
    const int br  = tid >> 5;
    const int bc4 = tid & 31;

    float acc[4][4][4];
#pragma unroll
    for (int mf = 0; mf < 4; mf++)
#pragma unroll
        for (int nf = 0; nf < 4; nf++)
#pragma unroll
            for (int r = 0; r < 4; r++) acc[mf][nf][r] = 0.0f;

    auto load_stage = [&](int slot, int chunk) {
        const uint32_t abase = sbase + slot * STAGE_BYTES;
        const uint32_t bbase = abase + A_BYTES;
        const int k0 = chunk * 32;
#pragma unroll
        for (int i = 0; i < 4; i++) {
            int r = ar + i * 32;
            int grow = rowBase + r;
            uint32_t dstp = abase + (r * ASTR + ac4 * 4) * 4;
            const uint32_t* srcp = A + (size_t)grow * K + k0 + ac4 * 4;
            cp_async16(dstp, srcp, (grow < M) ? 16u : 0u);
        }
#pragma unroll
        for (int i = 0; i < 4; i++) {
            int r = br + i * 8;
            uint32_t dstp = bbase + (r * BSTR + bc4 * 4) * 4;
            const uint32_t* srcp = B + (size_t)(k0 + r) * N + colBase + bc4 * 4;
            cp_async16(dstp, srcp, 16u);
        }
        CP_COMMIT();
    };

    load_stage(0, 0);
    if (NC > 1) load_stage(1, 1);

    for (int ci = 0; ci < NC; ci++) {
        CP_WAIT1();
        __syncthreads();

        int nci = ci + 2;
        if (nci < NC) load_stage(nci % NSTAGE, nci);

        const int slot = ci % NSTAGE;
        const uint32_t* As = reinterpret_cast<const uint32_t*>(sm + slot * STAGE_BYTES);
        const uint32_t* Bs = reinterpret_cast<const uint32_t*>(sm + slot * STAGE_BYTES + A_BYTES);

#pragma unroll
        for (int ks = 0; ks < 4; ks++) {
            uint32_t a[4][4];
#pragma unroll
            for (int mf = 0; mf < 4; mf++) {
                int mrow = wm * 64 + mf * 16 + qr;
                a[mf][0] = As[(mrow    ) * ASTR + ks * 8 + qc    ];
                a[mf][1] = As[(mrow + 8) * ASTR + ks * 8 + qc    ];
                a[mf][2] = As[(mrow    ) * ASTR + ks * 8 + qc + 4];
                a[mf][3] = As[(mrow + 8) * ASTR + ks * 8 + qc + 4];
            }
            uint32_t b[4][2];
#pragma unroll
            for (int nf = 0; nf < 4; nf++) {
                int ncol = wn * 32 + nf * 8 + qr;
                b[nf][0] = Bs[(ks * 8 + qc    ) * BSTR + ncol];
                b[nf][1] = Bs[(ks * 8 + qc + 4) * BSTR + ncol];
            }
#pragma unroll
            for (int mf = 0; mf < 4; mf++)
#pragma unroll
                for (int nf = 0; nf < 4; nf++) {
                    asm volatile(
                        "mma.sync.aligned.m16n8k8.row.col.f32.tf32.tf32.f32 "
                        "{%0,%1,%2,%3}, {%4,%5,%6,%7}, {%8,%9}, {%0,%1,%2,%3};"
                        : "+f"(acc[mf][nf][0]), "+f"(acc[mf][nf][1]),
                          "+f"(acc[mf][nf][2]), "+f"(acc[mf][nf][3])
                        : "r"(a[mf][0]), "r"(a[mf][1]), "r"(a[mf][2]), "r"(a[mf][3]),
                          "r"(b[nf][0]), "r"(b[nf][1]));
                }
        }
        __syncthreads();
    }

#pragma unroll
    for (int mf = 0; mf < 4; mf++) {
#pragma unroll
        for (int half = 0; half < 2; half++) {
            int grow = rowBase + wm * 64 + mf * 16 + qr + half * 8;
            if (grow >= M) continue;
#pragma unroll
            for (int nf = 0; nf < 4; nf++) {
                int gcol = colBase + wn * 32 + nf * 8 + 2 * qc;
                float x = acc[mf][nf][half * 2 + 0] + bias[gcol + 0];
                float y = acc[mf][nf][half * 2 + 1] + bias[gcol + 1];
                if (RELU) { x = fmaxf(x, 0.f); y = fmaxf(y, 0.f); }
                if (RESID) {
                    float2 r = *reinterpret_cast<const float2*>(
                        resid + (size_t)grow * N + gcol);
                    x += r.x; y += r.y;
                }
                if (OUT_TF32) {
                    uint2 t;
                    t.x = f32_to_tf32(x); t.y = f32_to_tf32(y);
                    *reinterpret_cast<uint2*>(Ct + (size_t)grow * N + gcol) = t;
                } else {
                    float2 v; v.x = x; v.y = y;
                    *reinterpret_cast<float2*>(Cf + (size_t)grow * N + gcol) = v;
                }
            }
        }
    }
}

// ---------------------------------------------------------------------------
extern "C" void kernel_launch(void* const* d_in, const int* in_sizes, int n_in,
                              void* d_out, int out_size) {
    const float* feat = (const float*)d_in[0];
    const float* W1   = (const float*)d_in[1];
    const float* b1   = (const float*)d_in[2];
    const float* W2   = (const float*)d_in[3];
    const float* b2   = (const float*)d_in[4];
    const float* eps  = (const float*)d_in[5];
    const int*   src  = (const int*)d_in[6];
    const int*   dst  = (const int*)d_in[7];
    const int n_edges = in_sizes[6];
    float* out = (float*)d_out;

    uint32_t *rstt = nullptr, *h = nullptr, *w1t = nullptr, *w2t = nullptr;
    int *cnt = nullptr, *off = nullptr, *cur = nullptr, *eidx = nullptr;
    cudaGetSymbolAddress((void**)&rstt, g_rst_t);
    cudaGetSymbolAddress((void**)&h, g_h);
    cudaGetSymbolAddress((void**)&w1t, g_w1t);
    cudaGetSymbolAddress((void**)&w2t, g_w2t);
    cudaGetSymbolAddress((void**)&cnt, g_cnt);
    cudaGetSymbolAddress((void**)&off, g_off);
    cudaGetSymbolAddress((void**)&cur, g_cur);
    cudaGetSymbolAddress((void**)&eidx, g_eidx);

    cudaFuncSetAttribute(gemm_async_kernel<true, false, true>,
                         cudaFuncAttributeMaxDynamicSharedMemorySize, GSM_TOTAL);
    cudaFuncSetAttribute(gemm_async_kernel<false, true, false>,
                         cudaFuncAttributeMaxDynamicSharedMemorySize, GSM_TOTAL);

    // 0) weights -> tf32
    {
        int n4 = D_IN * D_HID / 4;
        cvt_tf32_kernel<<<(n4 + 255) / 256, 256>>>(W1, w1t, n4);
        cvt_tf32_kernel<<<(n4 + 255) / 256, 256>>>(W2, w2t, n4);
    }
    // 1) CSR build
    zero_cnt_kernel<<<(N_NODES + 255) / 256, 256>>>(cnt, N_NODES);
    hist_kernel<<<(n_edges + 255) / 256, 256>>>(dst, cnt, n_edges);
    scan_kernel<<<1, 1024>>>(cnt, off, cur, N_NODES);
    fill_kernel<<<(n_edges + 255) / 256, 256>>>(src, dst, cur, eidx, n_edges);
    // 2) fused gather: rstt = tf32((1+eps)*feat + neighbor sum)
    {
        int warps_per_block = 256 / 32;
        int blocks = (N_NODES + warps_per_block - 1) / warps_per_block;
        gather_kernel<<<blocks, 256>>>(feat, eps, off, cnt, eidx, rstt);
    }
    // 3) h = tf32(relu(rst @ W1 + b1))
    {
        dim3 grid(D_HID / 128, (N_NODES + 127) / 128);
        gemm_async_kernel<true, false, true><<<grid, 256, GSM_TOTAL>>>(
            rstt, w1t, b1, nullptr, nullptr, h, N_NODES, D_HID, D_IN);
    }
    // 4) out = h @ W2 + b2 + feat
    {
        dim3 grid(D_IN / 128, (N_NODES + 127) / 128);
        gemm_async_kernel<false, true, false><<<grid, 256, GSM_TOTAL>>>(
            h, w2t, b2, feat, out, nullptr, N_NODES, D_IN, D_HID);
    }
}

// round 7
// speedup vs baseline: 3.0544x; 1.1196x over previous
#include <cuda_runtime.h>
#include <cstdint>

#define N_NODES 10000
#define N_EDGES_MAX 160000
#define D_IN    512
#define D_HID   1024

// ---------------- scratch (__device__ globals; no allocs) ------------------
__device__ uint32_t g_rst_t[N_NODES * D_IN];   // (1+eps)*feat + neigh sum, tf32
__device__ uint32_t g_h[N_NODES * D_HID];      // hidden activations as tf32
__device__ uint32_t g_w1t[D_IN * D_HID];       // W1^T tf32 [N=1024, K=512]
__device__ uint32_t g_w2t[D_HID * D_IN];       // W2^T tf32 [N=512, K=1024]
__device__ int      g_cnt[N_NODES];
__device__ int      g_off[N_NODES];
__device__ int      g_cur[N_NODES];
__device__ int      g_eidx[N_EDGES_MAX];

// ---------------- helpers --------------------------------------------------
__device__ __forceinline__ uint32_t f32_to_tf32(float f) {
    uint32_t r;
    asm("cvt.rna.tf32.f32 %0, %1;" : "=r"(r) : "f"(f));
    return r;
}
__device__ __forceinline__ uint32_t smem_u32(const void* p) {
    uint32_t a;
    asm("{ .reg .u64 t; cvta.to.shared.u64 t, %1; cvt.u32.u64 %0, t; }"
        : "=r"(a) : "l"(p));
    return a;
}
__device__ __forceinline__ void cp_async16(uint32_t dst, const void* src, uint32_t bytes) {
    asm volatile("cp.async.ca.shared.global [%0], [%1], 16, %2;"
                 :: "r"(dst), "l"(src), "r"(bytes) : "memory");
}
#define CP_COMMIT() asm volatile("cp.async.commit_group;" ::: "memory")
#define CP_WAIT1()  asm volatile("cp.async.wait_group 1;" ::: "memory")

// ---------------------------------------------------------------------------
// CSR build
// ---------------------------------------------------------------------------
__global__ void zero_cnt_kernel(int* __restrict__ cnt, int n) {
    int i = blockIdx.x * blockDim.x + threadIdx.x;
    if (i < n) cnt[i] = 0;
}
__global__ void hist_kernel(const int* __restrict__ dst, int* __restrict__ cnt,
                            int n_edges) {
    int i = blockIdx.x * blockDim.x + threadIdx.x;
    if (i < n_edges) atomicAdd(&cnt[dst[i]], 1);
}
__global__ __launch_bounds__(1024)
void scan_kernel(const int* __restrict__ cnt, int* __restrict__ off,
                 int* __restrict__ cur, int n) {
    __shared__ int buf[1024];
    __shared__ int carry;
    int tid = threadIdx.x;
    if (tid == 0) carry = 0;
    __syncthreads();
    for (int base = 0; base < n; base += 1024) {
        int v = (base + tid < n) ? cnt[base + tid] : 0;
        buf[tid] = v;
        __syncthreads();
#pragma unroll
        for (int s = 1; s < 1024; s <<= 1) {
            int t = (tid >= s) ? buf[tid - s] : 0;
            __syncthreads();
            buf[tid] += t;
            __syncthreads();
        }
        int incl = buf[tid];
        int c = carry;
        int tot = buf[1023];
        __syncthreads();
        if (base + tid < n) {
            int e = c + incl - v;
            off[base + tid] = e;
            cur[base + tid] = e;
        }
        if (tid == 0) carry = c + tot;
        __syncthreads();
    }
}
__global__ void fill_kernel(const int* __restrict__ src, const int* __restrict__ dst,
                            int* __restrict__ cur, int* __restrict__ eidx,
                            int n_edges) {
    int i = blockIdx.x * blockDim.x + threadIdx.x;
    if (i >= n_edges) return;
    int pos = atomicAdd(&cur[dst[i]], 1);
    eidx[pos] = src[i];
}

// ---------------------------------------------------------------------------
// Fused gather: one warp per dst node.
// ---------------------------------------------------------------------------
__global__ __launch_bounds__(256)
void gather_kernel(const float* __restrict__ feat, const float* __restrict__ eps,
                   const int* __restrict__ off, const int* __restrict__ cnt,
                   const int* __restrict__ eidx, uint32_t* __restrict__ rstt) {
    int warp = (blockIdx.x * blockDim.x + threadIdx.x) >> 5;
    int lane = threadIdx.x & 31;
    if (warp >= N_NODES) return;

    float acc[16];
    {
        float s = 1.0f + eps[0];
        const float4* fd = reinterpret_cast<const float4*>(feat + (size_t)warp * D_IN);
#pragma unroll
        for (int i = 0; i < 4; i++) {
            float4 v = fd[lane + i * 32];
            acc[i * 4 + 0] = s * v.x; acc[i * 4 + 1] = s * v.y;
            acc[i * 4 + 2] = s * v.z; acc[i * 4 + 3] = s * v.w;
        }
    }
    int beg = off[warp];
    int deg = cnt[warp];
    for (int j = 0; j < deg; j++) {
        int s = eidx[beg + j];
        const float4* fs = reinterpret_cast<const float4*>(feat + (size_t)s * D_IN);
#pragma unroll
        for (int i = 0; i < 4; i++) {
            float4 v = fs[lane + i * 32];
            acc[i * 4 + 0] += v.x; acc[i * 4 + 1] += v.y;
            acc[i * 4 + 2] += v.z; acc[i * 4 + 3] += v.w;
        }
    }
    uint32_t* ro = rstt + (size_t)warp * D_IN;
#pragma unroll
    for (int i = 0; i < 4; i++) {
        uint4 t;
        t.x = f32_to_tf32(acc[i * 4 + 0]); t.y = f32_to_tf32(acc[i * 4 + 1]);
        t.z = f32_to_tf32(acc[i * 4 + 2]); t.w = f32_to_tf32(acc[i * 4 + 3]);
        reinterpret_cast<uint4*>(ro)[lane + i * 32] = t;
    }
}

// ---------------------------------------------------------------------------
// transpose + f32->tf32:  WT[n*K + k] = tf32(W[k*N + n])
// ---------------------------------------------------------------------------
__global__ void transpose_tf32_kernel(const float* __restrict__ W,
                                      uint32_t* __restrict__ WT, int K, int N) {
    __shared__ float t[32][33];
    int n0 = blockIdx.x * 32, k0 = blockIdx.y * 32;
    int tx = threadIdx.x, ty = threadIdx.y;
#pragma unroll
    for (int j = 0; j < 4; j++)
        t[ty + j * 8][tx] = W[(size_t)(k0 + ty + j * 8) * N + n0 + tx];
    __syncthreads();
#pragma unroll
    for (int j = 0; j < 4; j++)
        WT[(size_t)(n0 + ty + j * 8) * K + k0 + tx] = f32_to_tf32(t[tx][ty + j * 8]);
}

// ---------------------------------------------------------------------------
// TF32 mma.sync GEMM, 3-stage cp.async pipeline, ldmatrix fragment loads.
//   C[M,N] = op(A[M,K] @ BT[N,K]^T + bias [+ resid])
// Both A and BT are tf32, K-contiguous. Tiles: 128 rows x 32 k-words,
// swizzled 16B units: addr(r,u) = r*128 + ((u ^ (r&7)) << 4).
// ---------------------------------------------------------------------------
#define TILE_B 16384                       // 128*32*4
#define STAGE_BYTES (2 * TILE_B)           // A + B
#define NSTAGE 3
#define GSM_TOTAL (NSTAGE * STAGE_BYTES)

template <bool RELU, bool RESID, bool OUT_TF32>
__global__ __launch_bounds__(256, 2)
void gemm_ldsm_kernel(const uint32_t* __restrict__ A, const uint32_t* __restrict__ BT,
                      const float* __restrict__ bias, const float* __restrict__ resid,
                      float* __restrict__ Cf, uint32_t* __restrict__ Ct,
                      int M, int N, int K) {
    extern __shared__ char sm[];
    const uint32_t sbase = smem_u32(sm);
    const int tid  = threadIdx.x;
    const int lane = tid & 31;
    const int wid  = tid >> 5;
    const int wm   = wid >> 2;        // 0..1 (M)
    const int wn   = wid & 3;         // 0..3 (N)
    const int qr   = lane >> 2;
    const int qc   = lane & 3;

    const int rowBase = blockIdx.y * 128;
    const int colBase = blockIdx.x * 128;
    const int NC = K >> 5;

    // producer coords: 1024 16B units per tile, 4 per thread
    const int pr  = tid >> 3;         // row base (lin>>3), +32 per i
    const int pu  = tid & 7;          // 16B unit within row

    // ldmatrix per-lane address components
    const int la15  = lane & 15;              // A row offset within 16
    const int ldu   = lane >> 4;              // A k-unit offset (0/1)
    const int lb_r  = ((lane >> 4) << 3) | (lane & 7);  // B row offset within 16
    const int lb_du = (lane >> 3) & 1;        // B k-unit offset

    float acc[4][4][4];
#pragma unroll
    for (int mf = 0; mf < 4; mf++)
#pragma unroll
        for (int nf = 0; nf < 4; nf++)
#pragma unroll
            for (int r = 0; r < 4; r++) acc[mf][nf][r] = 0.0f;

    auto load_stage = [&](int slot, int chunk) {
        const uint32_t abase = sbase + slot * STAGE_BYTES;
        const uint32_t bbase = abase + TILE_B;
        const int k0 = chunk * 32;
#pragma unroll
        for (int i = 0; i < 4; i++) {
            int r = pr + i * 32;
            int grow = rowBase + r;
            uint32_t dstp = abase + r * 128 + ((pu ^ (r & 7)) << 4);
            const uint32_t* srcp = A + (size_t)grow * K + k0 + pu * 4;
            cp_async16(dstp, srcp, (grow < M) ? 16u : 0u);
        }
#pragma unroll
        for (int i = 0; i < 4; i++) {
            int r = pr + i * 32;
            uint32_t dstp = bbase + r * 128 + ((pu ^ (r & 7)) << 4);
            const uint32_t* srcp = BT + (size_t)(colBase + r) * K + k0 + pu * 4;
            cp_async16(dstp, srcp, 16u);
        }
        CP_COMMIT();
    };

    load_stage(0, 0);
    if (NC > 1) load_stage(1, 1);

    for (int ci = 0; ci < NC; ci++) {
        CP_WAIT1();
        __syncthreads();

        int nci = ci + 2;
        if (nci < NC) load_stage(nci % NSTAGE, nci);

        const int slot = ci % NSTAGE;
        const uint32_t atile = sbase + slot * STAGE_BYTES;
        const uint32_t btile = atile + TILE_B;

#pragma unroll
        for (int ks = 0; ks < 4; ks++) {
            uint32_t a[4][4];
#pragma unroll
            for (int mf = 0; mf < 4; mf++) {
                int r = wm * 64 + mf * 16 + la15;
                uint32_t addr = atile + r * 128 + ((((ks << 1) + ldu) ^ (r & 7)) << 4);
                asm volatile(
                    "ldmatrix.sync.aligned.m8n8.x4.shared.b16 {%0,%1,%2,%3}, [%4];"
                    : "=r"(a[mf][0]), "=r"(a[mf][1]), "=r"(a[mf][2]), "=r"(a[mf][3])
                    : "r"(addr));
            }
            uint32_t b[4][2];
#pragma unroll
            for (int nf2 = 0; nf2 < 2; nf2++) {
                int r = wn * 32 + nf2 * 16 + lb_r;
                uint32_t addr = btile + r * 128 + ((((ks << 1) + lb_du) ^ (r & 7)) << 4);
                asm volatile(
                    "ldmatrix.sync.aligned.m8n8.x4.shared.b16 {%0,%1,%2,%3}, [%4];"
                    : "=r"(b[nf2 * 2][0]), "=r"(b[nf2 * 2][1]),
                      "=r"(b[nf2 * 2 + 1][0]), "=r"(b[nf2 * 2 + 1][1])
                    : "r"(addr));
            }
#pragma unroll
            for (int mf = 0; mf < 4; mf++)
#pragma unroll
                for (int nf = 0; nf < 4; nf++) {
                    asm volatile(
                        "mma.sync.aligned.m16n8k8.row.col.f32.tf32.tf32.f32 "
                        "{%0,%1,%2,%3}, {%4,%5,%6,%7}, {%8,%9}, {%0,%1,%2,%3};"
                        : "+f"(acc[mf][nf][0]), "+f"(acc[mf][nf][1]),
                          "+f"(acc[mf][nf][2]), "+f"(acc[mf][nf][3])
                        : "r"(a[mf][0]), "r"(a[mf][1]), "r"(a[mf][2]), "r"(a[mf][3]),
                          "r"(b[nf][0]), "r"(b[nf][1]));
                }
        }
        __syncthreads();
    }

    // ---- epilogue (mapping unchanged) ----
#pragma unroll
    for (int mf = 0; mf < 4; mf++) {
#pragma unroll
        for (int half = 0; half < 2; half++) {
            int grow = rowBase + wm * 64 + mf * 16 + qr + half * 8;
            if (grow >= M) continue;
#pragma unroll
            for (int nf = 0; nf < 4; nf++) {
                int gcol = colBase + wn * 32 + nf * 8 + 2 * qc;
                float x = acc[mf][nf][half * 2 + 0] + bias[gcol + 0];
                float y = acc[mf][nf][half * 2 + 1] + bias[gcol + 1];
                if (RELU) { x = fmaxf(x, 0.f); y = fmaxf(y, 0.f); }
                if (RESID) {
                    float2 r = *reinterpret_cast<const float2*>(
                        resid + (size_t)grow * N + gcol);
                    x += r.x; y += r.y;
                }
                if (OUT_TF32) {
                    uint2 t;
                    t.x = f32_to_tf32(x); t.y = f32_to_tf32(y);
                    *reinterpret_cast<uint2*>(Ct + (size_t)grow * N + gcol) = t;
                } else {
                    float2 v; v.x = x; v.y = y;
                    *reinterpret_cast<float2*>(Cf + (size_t)grow * N + gcol) = v;
                }
            }
        }
    }
}

// ---------------------------------------------------------------------------
extern "C" void kernel_launch(void* const* d_in, const int* in_sizes, int n_in,
                              void* d_out, int out_size) {
    const float* feat = (const float*)d_in[0];
    const float* W1   = (const float*)d_in[1];
    const float* b1   = (const float*)d_in[2];
    const float* W2   = (const float*)d_in[3];
    const float* b2   = (const float*)d_in[4];
    const float* eps  = (const float*)d_in[5];
    const int*   src  = (const int*)d_in[6];
    const int*   dst  = (const int*)d_in[7];
    const int n_edges = in_sizes[6];
    float* out = (float*)d_out;

    uint32_t *rstt = nullptr, *h = nullptr, *w1t = nullptr, *w2t = nullptr;
    int *cnt = nullptr, *off = nullptr, *cur = nullptr, *eidx = nullptr;
    cudaGetSymbolAddress((void**)&rstt, g_rst_t);
    cudaGetSymbolAddress((void**)&h, g_h);
    cudaGetSymbolAddress((void**)&w1t, g_w1t);
    cudaGetSymbolAddress((void**)&w2t, g_w2t);
    cudaGetSymbolAddress((void**)&cnt, g_cnt);
    cudaGetSymbolAddress((void**)&off, g_off);
    cudaGetSymbolAddress((void**)&cur, g_cur);
    cudaGetSymbolAddress((void**)&eidx, g_eidx);

    cudaFuncSetAttribute(gemm_ldsm_kernel<true, false, true>,
                         cudaFuncAttributeMaxDynamicSharedMemorySize, GSM_TOTAL);
    cudaFuncSetAttribute(gemm_ldsm_kernel<false, true, false>,
                         cudaFuncAttributeMaxDynamicSharedMemorySize, GSM_TOTAL);

    // 0) weights -> transposed tf32 [N, K]
    {
        dim3 blk(32, 8);
        transpose_tf32_kernel<<<dim3(D_HID / 32, D_IN / 32), blk>>>(W1, w1t, D_IN, D_HID);
        transpose_tf32_kernel<<<dim3(D_IN / 32, D_HID / 32), blk>>>(W2, w2t, D_HID, D_IN);
    }
    // 1) CSR build
    zero_cnt_kernel<<<(N_NODES + 255) / 256, 256>>>(cnt, N_NODES);
    hist_kernel<<<(n_edges + 255) / 256, 256>>>(dst, cnt, n_edges);
    scan_kernel<<<1, 1024>>>(cnt, off, cur, N_NODES);
    fill_kernel<<<(n_edges + 255) / 256, 256>>>(src, dst, cur, eidx, n_edges);
    // 2) fused gather
    {
        int blocks = (N_NODES + 7) / 8;
        gather_kernel<<<blocks, 256>>>(feat, eps, off, cnt, eidx, rstt);
    }
    // 3) h = tf32(relu(rst @ W1 + b1))
    {
        dim3 grid(D_HID / 128, (N_NODES + 127) / 128);
        gemm_ldsm_kernel<true, false, true><<<grid, 256, GSM_TOTAL>>>(
            rstt, w1t, b1, nullptr, nullptr, h, N_NODES, D_HID, D_IN);
    }
    // 4) out = h @ W2 + b2 + feat
    {
        dim3 grid(D_IN / 128, (N_NODES + 127) / 128);
        gemm_ldsm_kernel<false, true, false><<<grid, 256, GSM_TOTAL>>>(
            h, w2t, b2, feat, out, nullptr, N_NODES, D_IN, D_HID);
    }
}

// round 10
// speedup vs baseline: 5.1740x; 1.6939x over previous
#include <cuda_runtime.h>
#include <cuda_fp16.h>
#include <cstdint>

#define N_NODES 10000
#define N_EDGES_MAX 160000
#define D_IN    512
#define D_HID   1024
#define CAP     128                     // max in-degree bucket capacity

// ---------------- scratch (__device__ globals; no allocs) ------------------
__device__ __half g_rst_h[N_NODES * D_IN];   // (1+eps)*feat + neigh sum, fp16
__device__ __half g_h[N_NODES * D_HID];      // hidden activations, fp16
__device__ __half g_w1t[D_IN * D_HID];       // W1^T fp16 [N=1024, K=512]
__device__ __half g_w2t[D_HID * D_IN];       // W2^T fp16 [N=512, K=1024]
__device__ int    g_cnt[N_NODES];
__device__ int    g_eidx[N_NODES * CAP];

// ---------------- helpers --------------------------------------------------
__device__ __forceinline__ uint32_t smem_u32(const void* p) {
    uint32_t a;
    asm("{ .reg .u64 t; cvta.to.shared.u64 t, %1; cvt.u32.u64 %0, t; }"
        : "=r"(a) : "l"(p));
    return a;
}
__device__ __forceinline__ void cp_async16(uint32_t dst, const void* src, uint32_t bytes) {
    asm volatile("cp.async.ca.shared.global [%0], [%1], 16, %2;"
                 :: "r"(dst), "l"(src), "r"(bytes) : "memory");
}
#define CP_COMMIT() asm volatile("cp.async.commit_group;" ::: "memory")
#define CP_WAIT1()  asm volatile("cp.async.wait_group 1;" ::: "memory")

// ---------------------------------------------------------------------------
// Bucketed adjacency build (no scan): cnt zero + fill
// ---------------------------------------------------------------------------
__global__ void zero_cnt_kernel(int* __restrict__ cnt, int n) {
    int i = blockIdx.x * blockDim.x + threadIdx.x;
    if (i < n) cnt[i] = 0;
}
__global__ void fill_kernel(const int* __restrict__ src, const int* __restrict__ dst,
                            int* __restrict__ cnt, int* __restrict__ eidx,
                            int n_edges) {
    int i = blockIdx.x * blockDim.x + threadIdx.x;
    if (i >= n_edges) return;
    int d = dst[i];
    int pos = atomicAdd(&cnt[d], 1);
    eidx[d * CAP + pos] = src[i];
}

// ---------------------------------------------------------------------------
// Fused gather: one warp per dst node.
// rst[d] = (1+eps)*feat[d] + sum feat[s];  output fp16.
// Edge indices batch-loaded 32-at-a-time and broadcast via shfl.
// ---------------------------------------------------------------------------
__global__ __launch_bounds__(256)
void gather_kernel(const float* __restrict__ feat, const float* __restrict__ eps,
                   const int* __restrict__ cnt, const int* __restrict__ eidx,
                   __half* __restrict__ rsth) {
    int node = (blockIdx.x * blockDim.x + threadIdx.x) >> 5;
    int lane = threadIdx.x & 31;
    if (node >= N_NODES) return;

    float acc[16];
    {
        float s = 1.0f + eps[0];
        const float4* fd = reinterpret_cast<const float4*>(feat + (size_t)node * D_IN);
#pragma unroll
        for (int i = 0; i < 4; i++) {
            float4 v = fd[lane + i * 32];
            acc[i * 4 + 0] = s * v.x; acc[i * 4 + 1] = s * v.y;
            acc[i * 4 + 2] = s * v.z; acc[i * 4 + 3] = s * v.w;
        }
    }
    const int deg = cnt[node];
    const int* ep = eidx + (size_t)node * CAP;
    for (int j0 = 0; j0 < deg; j0 += 32) {
        int mine = (j0 + lane < deg) ? ep[j0 + lane] : 0;
        int m = deg - j0; if (m > 32) m = 32;
        for (int jj = 0; jj < m; jj++) {
            int s = __shfl_sync(0xFFFFFFFFu, mine, jj);
            const float4* fs = reinterpret_cast<const float4*>(feat + (size_t)s * D_IN);
#pragma unroll
            for (int i = 0; i < 4; i++) {
                float4 v = fs[lane + i * 32];
                acc[i * 4 + 0] += v.x; acc[i * 4 + 1] += v.y;
                acc[i * 4 + 2] += v.z; acc[i * 4 + 3] += v.w;
            }
        }
    }
    // write fp16: float4 block f -> half2 pair at half2-index 2f
    uint2* ro = reinterpret_cast<uint2*>(rsth + (size_t)node * D_IN);
#pragma unroll
    for (int i = 0; i < 4; i++) {
        __half2 lo = __floats2half2_rn(acc[i * 4 + 0], acc[i * 4 + 1]);
        __half2 hi = __floats2half2_rn(acc[i * 4 + 2], acc[i * 4 + 3]);
        uint2 t;
        t.x = *reinterpret_cast<uint32_t*>(&lo);
        t.y = *reinterpret_cast<uint32_t*>(&hi);
        ro[lane + i * 32] = t;
    }
}

// ---------------------------------------------------------------------------
// transpose + f32->fp16:  WT[n*K + k] = half(W[k*N + n])
// ---------------------------------------------------------------------------
__global__ void transpose_half_kernel(const float* __restrict__ W,
                                      __half* __restrict__ WT, int K, int N) {
    __shared__ float t[32][33];
    int n0 = blockIdx.x * 32, k0 = blockIdx.y * 32;
    int tx = threadIdx.x, ty = threadIdx.y;
#pragma unroll
    for (int j = 0; j < 4; j++)
        t[ty + j * 8][tx] = W[(size_t)(k0 + ty + j * 8) * N + n0 + tx];
    __syncthreads();
#pragma unroll
    for (int j = 0; j < 4; j++)
        WT[(size_t)(n0 + ty + j * 8) * K + k0 + tx] = __float2half_rn(t[tx][ty + j * 8]);
}

// ---------------------------------------------------------------------------
// FP16 mma.sync GEMM (f32 accumulate), 3-stage cp.async pipeline, ldmatrix.
//   C[M,N] = op(A[M,K] @ BT[N,K]^T + bias [+ resid])
// A, BT fp16 K-contiguous. Tiles: 128 rows x 64 halfs (128B/row),
// swizzled 16B units: addr(r,u) = r*128 + ((u ^ (r&7)) << 4).
// BK = 64 halfs -> 4 k-steps of m16n8k16 per chunk.
// ---------------------------------------------------------------------------
#define TILE_B 16384                       // 128 rows * 128 bytes
#define STAGE_BYTES (2 * TILE_B)
#define NSTAGE 3
#define GSM_TOTAL (NSTAGE * STAGE_BYTES)

template <bool RELU, bool RESID, bool OUT_HALF>
__global__ __launch_bounds__(256, 2)
void gemm_fp16_kernel(const __half* __restrict__ A, const __half* __restrict__ BT,
                      const float* __restrict__ bias, const float* __restrict__ resid,
                      float* __restrict__ Cf, __half* __restrict__ Ch,
                      int M, int N, int K) {
    extern __shared__ char sm[];
    const uint32_t sbase = smem_u32(sm);
    const int tid  = threadIdx.x;
    const int lane = tid & 31;
    const int wid  = tid >> 5;
    const int wm   = wid >> 2;        // 0..1 (M)
    const int wn   = wid & 3;         // 0..3 (N)
    const int qr   = lane >> 2;
    const int qc   = lane & 3;

    const int rowBase = blockIdx.y * 128;
    const int colBase = blockIdx.x * 128;
    const int NC = K >> 6;            // chunks of 64 halfs

    // producer coords: 1024 16B units per tile, 4 per thread
    const int pr = tid >> 3;          // row base, +32 per i
    const int pu = tid & 7;           // 16B unit within row (8 halfs)

    // ldmatrix per-lane address components (identical mapping to tf32 path)
    const int la15  = lane & 15;
    const int ldu   = lane >> 4;
    const int lb_r  = ((lane >> 4) << 3) | (lane & 7);
    const int lb_du = (lane >> 3) & 1;

    float acc[4][4][4];
#pragma unroll
    for (int mf = 0; mf < 4; mf++)
#pragma unroll
        for (int nf = 0; nf < 4; nf++)
#pragma unroll
            for (int r = 0; r < 4; r++) acc[mf][nf][r] = 0.0f;

    auto load_stage = [&](int slot, int chunk) {
        const uint32_t abase = sbase + slot * STAGE_BYTES;
        const uint32_t bbase = abase + TILE_B;
        const int k0 = chunk * 64;    // halfs
#pragma unroll
        for (int i = 0; i < 4; i++) {
            int r = pr + i * 32;
            int grow = rowBase + r;
            uint32_t dstp = abase + r * 128 + ((pu ^ (r & 7)) << 4);
            const __half* srcp = A + (size_t)grow * K + k0 + pu * 8;
            cp_async16(dstp, srcp, (grow < M) ? 16u : 0u);
        }
#pragma unroll
        for (int i = 0; i < 4; i++) {
            int r = pr + i * 32;
            uint32_t dstp = bbase + r * 128 + ((pu ^ (r & 7)) << 4);
            const __half* srcp = BT + (size_t)(colBase + r) * K + k0 + pu * 8;
            cp_async16(dstp, srcp, 16u);
        }
        CP_COMMIT();
    };

    load_stage(0, 0);
    if (NC > 1) load_stage(1, 1);

    for (int ci = 0; ci < NC; ci++) {
        CP_WAIT1();
        __syncthreads();

        int nci = ci + 2;
        if (nci < NC) load_stage(nci % NSTAGE, nci);

        const int slot = ci % NSTAGE;
        const uint32_t atile = sbase + slot * STAGE_BYTES;
        const uint32_t btile = atile + TILE_B;

#pragma unroll
        for (int ks = 0; ks < 4; ks++) {   // 4 x k16
            uint32_t a[4][4];
#pragma unroll
            for (int mf = 0; mf < 4; mf++) {
                int r = wm * 64 + mf * 16 + la15;
                uint32_t addr = atile + r * 128 + ((((ks << 1) + ldu) ^ (r & 7)) << 4);
                asm volatile(
                    "ldmatrix.sync.aligned.m8n8.x4.shared.b16 {%0,%1,%2,%3}, [%4];"
                    : "=r"(a[mf][0]), "=r"(a[mf][1]), "=r"(a[mf][2]), "=r"(a[mf][3])
                    : "r"(addr));
            }
            uint32_t b[4][2];
#pragma unroll
            for (int nf2 = 0; nf2 < 2; nf2++) {
                int r = wn * 32 + nf2 * 16 + lb_r;
                uint32_t addr = btile + r * 128 + ((((ks << 1) + lb_du) ^ (r & 7)) << 4);
                asm volatile(
                    "ldmatrix.sync.aligned.m8n8.x4.shared.b16 {%0,%1,%2,%3}, [%4];"
                    : "=r"(b[nf2 * 2][0]), "=r"(b[nf2 * 2][1]),
                      "=r"(b[nf2 * 2 + 1][0]), "=r"(b[nf2 * 2 + 1][1])
                    : "r"(addr));
            }
#pragma unroll
            for (int mf = 0; mf < 4; mf++)
#pragma unroll
                for (int nf = 0; nf < 4; nf++) {
                    asm volatile(
                        "mma.sync.aligned.m16n8k16.row.col.f32.f16.f16.f32 "
                        "{%0,%1,%2,%3}, {%4,%5,%6,%7}, {%8,%9}, {%0,%1,%2,%3};"
                        : "+f"(acc[mf][nf][0]), "+f"(acc[mf][nf][1]),
                          "+f"(acc[mf][nf][2]), "+f"(acc[mf][nf][3])
                        : "r"(a[mf][0]), "r"(a[mf][1]), "r"(a[mf][2]), "r"(a[mf][3]),
                          "r"(b[nf][0]), "r"(b[nf][1]));
                }
        }
        __syncthreads();
    }

    // ---- epilogue: c0,c1 at (qr, 2qc); c2,c3 at (qr+8, 2qc) ----
#pragma unroll
    for (int mf = 0; mf < 4; mf++) {
#pragma unroll
        for (int half = 0; half < 2; half++) {
            int grow = rowBase + wm * 64 + mf * 16 + qr + half * 8;
            if (grow >= M) continue;
#pragma unroll
            for (int nf = 0; nf < 4; nf++) {
                int gcol = colBase + wn * 32 + nf * 8 + 2 * qc;
                float x = acc[mf][nf][half * 2 + 0] + bias[gcol + 0];
                float y = acc[mf][nf][half * 2 + 1] + bias[gcol + 1];
                if (RELU) { x = fmaxf(x, 0.f); y = fmaxf(y, 0.f); }
                if (RESID) {
                    float2 r = *reinterpret_cast<const float2*>(
                        resid + (size_t)grow * N + gcol);
                    x += r.x; y += r.y;
                }
                if (OUT_HALF) {
                    __half2 hv = __floats2half2_rn(x, y);
                    *reinterpret_cast<uint32_t*>(Ch + (size_t)grow * N + gcol) =
                        *reinterpret_cast<uint32_t*>(&hv);
                } else {
                    float2 v; v.x = x; v.y = y;
                    *reinterpret_cast<float2*>(Cf + (size_t)grow * N + gcol) = v;
                }
            }
        }
    }
}

// ---------------------------------------------------------------------------
extern "C" void kernel_launch(void* const* d_in, const int* in_sizes, int n_in,
                              void* d_out, int out_size) {
    const float* feat = (const float*)d_in[0];
    const float* W1   = (const float*)d_in[1];
    const float* b1   = (const float*)d_in[2];
    const float* W2   = (const float*)d_in[3];
    const float* b2   = (const float*)d_in[4];
    const float* eps  = (const float*)d_in[5];
    const int*   src  = (const int*)d_in[6];
    const int*   dst  = (const int*)d_in[7];
    const int n_edges = in_sizes[6];
    float* out = (float*)d_out;

    __half *rsth = nullptr, *h = nullptr, *w1t = nullptr, *w2t = nullptr;
    int *cnt = nullptr, *eidx = nullptr;
    cudaGetSymbolAddress((void**)&rsth, g_rst_h);
    cudaGetSymbolAddress((void**)&h, g_h);
    cudaGetSymbolAddress((void**)&w1t, g_w1t);
    cudaGetSymbolAddress((void**)&w2t, g_w2t);
    cudaGetSymbolAddress((void**)&cnt, g_cnt);
    cudaGetSymbolAddress((void**)&eidx, g_eidx);

    cudaFuncSetAttribute(gemm_fp16_kernel<true, false, true>,
                         cudaFuncAttributeMaxDynamicSharedMemorySize, GSM_TOTAL);
    cudaFuncSetAttribute(gemm_fp16_kernel<false, true, false>,
                         cudaFuncAttributeMaxDynamicSharedMemorySize, GSM_TOTAL);

    // 0) weights -> transposed fp16 [N, K]
    {
        dim3 blk(32, 8);
        transpose_half_kernel<<<dim3(D_HID / 32, D_IN / 32), blk>>>(W1, w1t, D_IN, D_HID);
        transpose_half_kernel<<<dim3(D_IN / 32, D_HID / 32), blk>>>(W2, w2t, D_HID, D_IN);
    }
    // 1) adjacency buckets
    zero_cnt_kernel<<<(N_NODES + 255) / 256, 256>>>(cnt, N_NODES);
    fill_kernel<<<(n_edges + 255) / 256, 256>>>(src, dst, cnt, eidx, n_edges);
    // 2) fused gather -> fp16
    {
        int blocks = (N_NODES + 7) / 8;
        gather_kernel<<<blocks, 256>>>(feat, eps, cnt, eidx, rsth);
    }
    // 3) h = fp16(relu(rst @ W1 + b1))
    {
        dim3 grid(D_HID / 128, (N_NODES + 127) / 128);
        gemm_fp16_kernel<true, false, true><<<grid, 256, GSM_TOTAL>>>(
            rsth, w1t, b1, nullptr, nullptr, h, N_NODES, D_HID, D_IN);
    }
    // 4) out = h @ W2 + b2 + feat
    {
        dim3 grid(D_IN / 128, (N_NODES + 127) / 128);
        gemm_fp16_kernel<false, true, false><<<grid, 256, GSM_TOTAL>>>(
            h, w2t, b2, feat, out, nullptr, N_NODES, D_IN, D_HID);
    }
}

// round 12
// speedup vs baseline: 5.3507x; 1.0341x over previous
#include <cuda_runtime.h>
#include <cuda_fp16.h>
#include <cstdint>

#define N_NODES 10000
#define N_EDGES_MAX 160000
#define D_IN    512
#define D_HID   1024
#define CAP     128                     // max in-degree bucket capacity

// ---------------- scratch (__device__ globals; no allocs) ------------------
__device__ __half g_feat_h[N_NODES * D_IN];  // feat as fp16
__device__ __half g_rst_h[N_NODES * D_IN];   // (1+eps)*feat + neigh sum, fp16
__device__ __half g_h[N_NODES * D_HID];      // hidden activations, fp16
__device__ __half g_w1t[D_IN * D_HID];       // W1^T fp16 [N=1024, K=512]
__device__ __half g_w2t[D_HID * D_IN];       // W2^T fp16 [N=512, K=1024]
__device__ int    g_cnt[N_NODES];
__device__ int    g_eidx[N_NODES * CAP];

// ---------------- helpers --------------------------------------------------
__device__ __forceinline__ uint32_t smem_u32(const void* p) {
    uint32_t a;
    asm("{ .reg .u64 t; cvta.to.shared.u64 t, %1; cvt.u32.u64 %0, t; }"
        : "=r"(a) : "l"(p));
    return a;
}
__device__ __forceinline__ void cp_async16(uint32_t dst, const void* src, uint32_t bytes) {
    asm volatile("cp.async.ca.shared.global [%0], [%1], 16, %2;"
                 :: "r"(dst), "l"(src), "r"(bytes) : "memory");
}
#define CP_COMMIT() asm volatile("cp.async.commit_group;" ::: "memory")
#define CP_WAIT1()  asm volatile("cp.async.wait_group 1;" ::: "memory")

// ---------------------------------------------------------------------------
// feat f32 -> fp16 (8 halfs per thread)
// ---------------------------------------------------------------------------
__global__ void cvt_feat_half_kernel(const float* __restrict__ in,
                                     __half* __restrict__ out, int n8) {
    int i = blockIdx.x * blockDim.x + threadIdx.x;
    if (i >= n8) return;
    float4 a = reinterpret_cast<const float4*>(in)[i * 2];
    float4 b = reinterpret_cast<const float4*>(in)[i * 2 + 1];
    __half2 h0 = __floats2half2_rn(a.x, a.y);
    __half2 h1 = __floats2half2_rn(a.z, a.w);
    __half2 h2 = __floats2half2_rn(b.x, b.y);
    __half2 h3 = __floats2half2_rn(b.z, b.w);
    uint4 t;
    t.x = *reinterpret_cast<uint32_t*>(&h0);
    t.y = *reinterpret_cast<uint32_t*>(&h1);
    t.z = *reinterpret_cast<uint32_t*>(&h2);
    t.w = *reinterpret_cast<uint32_t*>(&h3);
    reinterpret_cast<uint4*>(out)[i] = t;
}

// ---------------------------------------------------------------------------
// Bucketed adjacency build
// ---------------------------------------------------------------------------
__global__ void zero_cnt_kernel(int* __restrict__ cnt, int n) {
    int i = blockIdx.x * blockDim.x + threadIdx.x;
    if (i < n) cnt[i] = 0;
}
__global__ void fill_kernel(const int* __restrict__ src, const int* __restrict__ dst,
                            int* __restrict__ cnt, int* __restrict__ eidx,
                            int n_edges) {
    int base = (blockIdx.x * blockDim.x + threadIdx.x) * 4;
#pragma unroll
    for (int j = 0; j < 4; j++) {
        int i = base + j;
        if (i < n_edges) {
            int d = dst[i];
            int pos = atomicAdd(&cnt[d], 1);
            eidx[d * CAP + pos] = src[i];
        }
    }
}

// ---------------------------------------------------------------------------
// Fused gather (fp16 feat): one warp per dst node.
// rst[d] = (1+eps)*feat[d] + sum feat[s];  f32 accumulate, fp16 out.
// Row = 512 halfs = 64 uint4 units; lane handles units {lane, lane+32}.
// ---------------------------------------------------------------------------
__global__ __launch_bounds__(256)
void gather_kernel(const __half* __restrict__ feath, const float* __restrict__ eps,
                   const int* __restrict__ cnt, const int* __restrict__ eidx,
                   __half* __restrict__ rsth) {
    int node = (blockIdx.x * blockDim.x + threadIdx.x) >> 5;
    int lane = threadIdx.x & 31;
    if (node >= N_NODES) return;

    float acc[16];
    {
        float s = 1.0f + eps[0];
        const uint4* fd = reinterpret_cast<const uint4*>(feath + (size_t)node * D_IN);
#pragma unroll
        for (int i = 0; i < 2; i++) {
            uint4 u = fd[lane + i * 32];
            const __half2* hp = reinterpret_cast<const __half2*>(&u);
#pragma unroll
            for (int q = 0; q < 4; q++) {
                float2 f = __half22float2(hp[q]);
                acc[i * 8 + q * 2 + 0] = s * f.x;
                acc[i * 8 + q * 2 + 1] = s * f.y;
            }
        }
    }
    const int deg = cnt[node];
    const int* ep = eidx + (size_t)node * CAP;
    for (int j0 = 0; j0 < deg; j0 += 32) {
        int mine = (j0 + lane < deg) ? ep[j0 + lane] : 0;
        int m = deg - j0; if (m > 32) m = 32;
        for (int jj = 0; jj < m; jj++) {
            int s = __shfl_sync(0xFFFFFFFFu, mine, jj);
            const uint4* fs = reinterpret_cast<const uint4*>(feath + (size_t)s * D_IN);
#pragma unroll
            for (int i = 0; i < 2; i++) {
                uint4 u = fs[lane + i * 32];
                const __half2* hp = reinterpret_cast<const __half2*>(&u);
#pragma unroll
                for (int q = 0; q < 4; q++) {
                    float2 f = __half22float2(hp[q]);
                    acc[i * 8 + q * 2 + 0] += f.x;
                    acc[i * 8 + q * 2 + 1] += f.y;
                }
            }
        }
    }
    uint4* ro = reinterpret_cast<uint4*>(rsth + (size_t)node * D_IN);
#pragma unroll
    for (int i = 0; i < 2; i++) {
        __half2 h0 = __floats2half2_rn(acc[i * 8 + 0], acc[i * 8 + 1]);
        __half2 h1 = __floats2half2_rn(acc[i * 8 + 2], acc[i * 8 + 3]);
        __half2 h2 = __floats2half2_rn(acc[i * 8 + 4], acc[i * 8 + 5]);
        __half2 h3 = __floats2half2_rn(acc[i * 8 + 6], acc[i * 8 + 7]);
        uint4 t;
        t.x = *reinterpret_cast<uint32_t*>(&h0);
        t.y = *reinterpret_cast<uint32_t*>(&h1);
        t.z = *reinterpret_cast<uint32_t*>(&h2);
        t.w = *reinterpret_cast<uint32_t*>(&h3);
        ro[lane + i * 32] = t;
    }
}

// ---------------------------------------------------------------------------
// transpose + f32->fp16:  WT[n*K + k] = half(W[k*N + n])
// ---------------------------------------------------------------------------
__global__ void transpose_half_kernel(const float* __restrict__ W,
                                      __half* __restrict__ WT, int K, int N) {
    __shared__ float t[32][33];
    int n0 = blockIdx.x * 32, k0 = blockIdx.y * 32;
    int tx = threadIdx.x, ty = threadIdx.y;
#pragma unroll
    for (int j = 0; j < 4; j++)
        t[ty + j * 8][tx] = W[(size_t)(k0 + ty + j * 8) * N + n0 + tx];
    __syncthreads();
#pragma unroll
    for (int j = 0; j < 4; j++)
        WT[(size_t)(n0 + ty + j * 8) * K + k0 + tx] = __float2half_rn(t[tx][ty + j * 8]);
}

// ---------------------------------------------------------------------------
// FP16 mma.sync GEMM (f32 accumulate), 3-stage cp.async pipeline, ldmatrix.
// ---------------------------------------------------------------------------
#define TILE_B 16384
#define STAGE_BYTES (2 * TILE_B)
#define NSTAGE 3
#define GSM_TOTAL (NSTAGE * STAGE_BYTES)

template <bool RELU, bool RESID, bool OUT_HALF>
__global__ __launch_bounds__(256, 2)
void gemm_fp16_kernel(const __half* __restrict__ A, const __half* __restrict__ BT,
                      const float* __restrict__ bias, const float* __restrict__ resid,
                      float* __restrict__ Cf, __half* __restrict__ Ch,
                      int M, int N, int K) {
    extern __shared__ char sm[];
    const uint32_t sbase = smem_u32(sm);
    const int tid  = threadIdx.x;
    const int lane = tid & 31;
    const int wid  = tid >> 5;
    const int wm   = wid >> 2;
    const int wn   = wid & 3;
    const int qr   = lane >> 2;
    const int qc   = lane & 3;

    const int rowBase = blockIdx.y * 128;
    const int colBase = blockIdx.x * 128;
    const int NC = K >> 6;

    const int pr = tid >> 3;
    const int pu = tid & 7;

    const int la15  = lane & 15;
    const int ldu   = lane >> 4;
    const int lb_r  = ((lane >> 4) << 3) | (lane & 7);
    const int lb_du = (lane >> 3) & 1;

    float acc[4][4][4];
#pragma unroll
    for (int mf = 0; mf < 4; mf++)
#pragma unroll
        for (int nf = 0; nf < 4; nf++)
#pragma unroll
            for (int r = 0; r < 4; r++) acc[mf][nf][r] = 0.0f;

    auto load_stage = [&](int slot, int chunk) {
        const uint32_t abase = sbase + slot * STAGE_BYTES;
        const uint32_t bbase = abase + TILE_B;
        const int k0 = chunk * 64;
#pragma unroll
        for (int i = 0; i < 4; i++) {
            int r = pr + i * 32;
            int grow = rowBase + r;
            uint32_t dstp = abase + r * 128 + ((pu ^ (r & 7)) << 4);
            const __half* srcp = A + (size_t)grow * K + k0 + pu * 8;
            cp_async16(dstp, srcp, (grow < M) ? 16u : 0u);
        }
#pragma unroll
        for (int i = 0; i < 4; i++) {
            int r = pr + i * 32;
            uint32_t dstp = bbase + r * 128 + ((pu ^ (r & 7)) << 4);
            const __half* srcp = BT + (size_t)(colBase + r) * K + k0 + pu * 8;
            cp_async16(dstp, srcp, 16u);
        }
        CP_COMMIT();
    };

    load_stage(0, 0);
    if (NC > 1) load_stage(1, 1);

    for (int ci = 0; ci < NC; ci++) {
        CP_WAIT1();
        __syncthreads();

        int nci = ci + 2;
        if (nci < NC) load_stage(nci % NSTAGE, nci);

        const int slot = ci % NSTAGE;
        const uint32_t atile = sbase + slot * STAGE_BYTES;
        const uint32_t btile = atile + TILE_B;

#pragma unroll
        for (int ks = 0; ks < 4; ks++) {
            uint32_t a[4][4];
#pragma unroll
            for (int mf = 0; mf < 4; mf++) {
                int r = wm * 64 + mf * 16 + la15;
                uint32_t addr = atile + r * 128 + ((((ks << 1) + ldu) ^ (r & 7)) << 4);
                asm volatile(
                    "ldmatrix.sync.aligned.m8n8.x4.shared.b16 {%0,%1,%2,%3}, [%4];"
                    : "=r"(a[mf][0]), "=r"(a[mf][1]), "=r"(a[mf][2]), "=r"(a[mf][3])
                    : "r"(addr));
            }
            uint32_t b[4][2];
#pragma unroll
            for (int nf2 = 0; nf2 < 2; nf2++) {
                int r = wn * 32 + nf2 * 16 + lb_r;
                uint32_t addr = btile + r * 128 + ((((ks << 1) + lb_du) ^ (r & 7)) << 4);
                asm volatile(
                    "ldmatrix.sync.aligned.m8n8.x4.shared.b16 {%0,%1,%2,%3}, [%4];"
                    : "=r"(b[nf2 * 2][0]), "=r"(b[nf2 * 2][1]),
                      "=r"(b[nf2 * 2 + 1][0]), "=r"(b[nf2 * 2 + 1][1])
                    : "r"(addr));
            }
#pragma unroll
            for (int mf = 0; mf < 4; mf++)
#pragma unroll
                for (int nf = 0; nf < 4; nf++) {
                    asm volatile(
                        "mma.sync.aligned.m16n8k16.row.col.f32.f16.f16.f32 "
                        "{%0,%1,%2,%3}, {%4,%5,%6,%7}, {%8,%9}, {%0,%1,%2,%3};"
                        : "+f"(acc[mf][nf][0]), "+f"(acc[mf][nf][1]),
                          "+f"(acc[mf][nf][2]), "+f"(acc[mf][nf][3])
                        : "r"(a[mf][0]), "r"(a[mf][1]), "r"(a[mf][2]), "r"(a[mf][3]),
                          "r"(b[nf][0]), "r"(b[nf][1]));
                }
        }
        __syncthreads();
    }

#pragma unroll
    for (int mf = 0; mf < 4; mf++) {
#pragma unroll
        for (int half = 0; half < 2; half++) {
            int grow = rowBase + wm * 64 + mf * 16 + qr + half * 8;
            if (grow >= M) continue;
#pragma unroll
            for (int nf = 0; nf < 4; nf++) {
                int gcol = colBase + wn * 32 + nf * 8 + 2 * qc;
                float x = acc[mf][nf][half * 2 + 0] + bias[gcol + 0];
                float y = acc[mf][nf][half * 2 + 1] + bias[gcol + 1];
                if (RELU) { x = fmaxf(x, 0.f); y = fmaxf(y, 0.f); }
                if (RESID) {
                    float2 r = *reinterpret_cast<const float2*>(
                        resid + (size_t)grow * N + gcol);
                    x += r.x; y += r.y;
                }
                if (OUT_HALF) {
                    __half2 hv = __floats2half2_rn(x, y);
                    *reinterpret_cast<uint32_t*>(Ch + (size_t)grow * N + gcol) =
                        *reinterpret_cast<uint32_t*>(&hv);
                } else {
                    float2 v; v.x = x; v.y = y;
                    *reinterpret_cast<float2*>(Cf + (size_t)grow * N + gcol) = v;
                }
            }
        }
    }
}

// ---------------------------------------------------------------------------
extern "C" void kernel_launch(void* const* d_in, const int* in_sizes, int n_in,
                              void* d_out, int out_size) {
    const float* feat = (const float*)d_in[0];
    const float* W1   = (const float*)d_in[1];
    const float* b1   = (const float*)d_in[2];
    const float* W2   = (const float*)d_in[3];
    const float* b2   = (const float*)d_in[4];
    const float* eps  = (const float*)d_in[5];
    const int*   src  = (const int*)d_in[6];
    const int*   dst  = (const int*)d_in[7];
    const int n_edges = in_sizes[6];
    float* out = (float*)d_out;

    __half *feath = nullptr, *rsth = nullptr, *h = nullptr, *w1t = nullptr, *w2t = nullptr;
    int *cnt = nullptr, *eidx = nullptr;
    cudaGetSymbolAddress((void**)&feath, g_feat_h);
    cudaGetSymbolAddress((void**)&rsth, g_rst_h);
    cudaGetSymbolAddress((void**)&h, g_h);
    cudaGetSymbolAddress((void**)&w1t, g_w1t);
    cudaGetSymbolAddress((void**)&w2t, g_w2t);
    cudaGetSymbolAddress((void**)&cnt, g_cnt);
    cudaGetSymbolAddress((void**)&eidx, g_eidx);

    cudaFuncSetAttribute(gemm_fp16_kernel<true, false, true>,
                         cudaFuncAttributeMaxDynamicSharedMemorySize, GSM_TOTAL);
    cudaFuncSetAttribute(gemm_fp16_kernel<false, true, false>,
                         cudaFuncAttributeMaxDynamicSharedMemorySize, GSM_TOTAL);

    // 0) feat -> fp16; weights -> transposed fp16 [N, K]
    {
        int n8 = N_NODES * D_IN / 8;
        cvt_feat_half_kernel<<<(n8 + 255) / 256, 256>>>(feat, feath, n8);
        dim3 blk(32, 8);
        transpose_half_kernel<<<dim3(D_HID / 32, D_IN / 32), blk>>>(W1, w1t, D_IN, D_HID);
        transpose_half_kernel<<<dim3(D_IN / 32, D_HID / 32), blk>>>(W2, w2t, D_HID, D_IN);
    }
    // 1) adjacency buckets
    zero_cnt_kernel<<<(N_NODES + 255) / 256, 256>>>(cnt, N_NODES);
    {
        int threads_needed = (n_edges + 3) / 4;
        fill_kernel<<<(threads_needed + 255) / 256, 256>>>(src, dst, cnt, eidx, n_edges);
    }
    // 2) fused gather (fp16 feat) -> fp16 rst
    {
        int blocks = (N_NODES + 7) / 8;
        gather_kernel<<<blocks, 256>>>(feath, eps, cnt, eidx, rsth);
    }
    // 3) h = fp16(relu(rst @ W1 + b1))
    {
        dim3 grid(D_HID / 128, (N_NODES + 127) / 128);
        gemm_fp16_kernel<true, false, true><<<grid, 256, GSM_TOTAL>>>(
            rsth, w1t, b1, nullptr, nullptr, h, N_NODES, D_HID, D_IN);
    }
    // 4) out = h @ W2 + b2 + feat
    {
        dim3 grid(D_IN / 128, (N_NODES + 127) / 128);
        gemm_fp16_kernel<false, true, false><<<grid, 256, GSM_TOTAL>>>(
            h, w2t, b2, feat, out, nullptr, N_NODES, D_IN, D_HID);
    }
}

// round 14
// speedup vs baseline: 5.4505x; 1.0187x over previous
#include <cuda_runtime.h>
#include <cuda_fp16.h>
#include <cstdint>

#define N_NODES 10000
#define N_EDGES_MAX 160000
#define D_IN    512
#define D_HID   1024
#define CAP     128                     // max in-degree bucket capacity

// ---------------- scratch (__device__ globals; no allocs) ------------------
__device__ __half g_feat_h[N_NODES * D_IN];  // feat as fp16
__device__ __half g_rst_h[N_NODES * D_IN];   // (1+eps)*feat + neigh sum, fp16
__device__ __half g_h[N_NODES * D_HID];      // hidden activations, fp16
__device__ __half g_w1t[D_IN * D_HID];       // W1^T fp16 [N=1024, K=512]
__device__ __half g_w2t[D_HID * D_IN];       // W2^T fp16 [N=512, K=1024]
__device__ int    g_cnt[N_NODES];
__device__ int    g_eidx[N_NODES * CAP];

// ---------------- helpers --------------------------------------------------
__device__ __forceinline__ uint32_t smem_u32(const void* p) {
    uint32_t a;
    asm("{ .reg .u64 t; cvta.to.shared.u64 t, %1; cvt.u32.u64 %0, t; }"
        : "=r"(a) : "l"(p));
    return a;
}
__device__ __forceinline__ void cp_async16(uint32_t dst, const void* src, uint32_t bytes) {
    asm volatile("cp.async.ca.shared.global [%0], [%1], 16, %2;"
                 :: "r"(dst), "l"(src), "r"(bytes) : "memory");
}
#define CP_COMMIT() asm volatile("cp.async.commit_group;" ::: "memory")
#define CP_WAIT1()  asm volatile("cp.async.wait_group 1;" ::: "memory")

__device__ __forceinline__ void acc_u4(float* a, uint4 u) {
    const __half2* hp = reinterpret_cast<const __half2*>(&u);
#pragma unroll
    for (int q = 0; q < 4; q++) {
        float2 f = __half22float2(hp[q]);
        a[q * 2 + 0] += f.x;
        a[q * 2 + 1] += f.y;
    }
}

// ---------------------------------------------------------------------------
// Fused prep kernel (one launch):
//   [0, NB_CVT)                : feat f32 -> fp16
//   [NB_CVT, +NB_T1)           : transpose+cvt W1 -> w1t [1024, 512]
//   [.., +NB_T2)               : transpose+cvt W2 -> w2t [512, 1024]
//   [.., +NB_ZERO)             : zero cnt
// all 256-thread blocks.
// ---------------------------------------------------------------------------
#define NB_CVT  2500                         // 640000 / 256
#define NB_T1   512                          // (1024/32)*(512/32)
#define NB_T2   512
#define NB_ZERO 40
#define NB_PREP (NB_CVT + NB_T1 + NB_T2 + NB_ZERO)

__device__ __forceinline__ void do_transpose(const float* __restrict__ W,
                                             __half* __restrict__ WT,
                                             int K, int N, int bx, int by,
                                             int tx, int ty) {
    __shared__ float t[32][33];
    int n0 = bx * 32, k0 = by * 32;
#pragma unroll
    for (int j = 0; j < 4; j++)
        t[ty + j * 8][tx] = W[(size_t)(k0 + ty + j * 8) * N + n0 + tx];
    __syncthreads();
#pragma unroll
    for (int j = 0; j < 4; j++)
        WT[(size_t)(n0 + ty + j * 8) * K + k0 + tx] = __float2half_rn(t[tx][ty + j * 8]);
}

__global__ __launch_bounds__(256)
void prep_kernel(const float* __restrict__ feat,
                 const float* __restrict__ W1, const float* __restrict__ W2,
                 __half* __restrict__ feath, __half* __restrict__ w1t,
                 __half* __restrict__ w2t, int* __restrict__ cnt) {
    int b = blockIdx.x;
    int tid = threadIdx.x;
    if (b < NB_CVT) {
        int i = b * 256 + tid;               // uint4 index (8 halfs)
        float4 a = reinterpret_cast<const float4*>(feat)[i * 2];
        float4 c = reinterpret_cast<const float4*>(feat)[i * 2 + 1];
        __half2 h0 = __floats2half2_rn(a.x, a.y);
        __half2 h1 = __floats2half2_rn(a.z, a.w);
        __half2 h2 = __floats2half2_rn(c.x, c.y);
        __half2 h3 = __floats2half2_rn(c.z, c.w);
        uint4 t;
        t.x = *reinterpret_cast<uint32_t*>(&h0);
        t.y = *reinterpret_cast<uint32_t*>(&h1);
        t.z = *reinterpret_cast<uint32_t*>(&h2);
        t.w = *reinterpret_cast<uint32_t*>(&h3);
        reinterpret_cast<uint4*>(feath)[i] = t;
    } else if (b < NB_CVT + NB_T1) {
        int bb = b - NB_CVT;                 // W1: N=1024 -> 32 bx, K=512 -> 16 by
        do_transpose(W1, w1t, D_IN, D_HID, bb & 31, bb >> 5, tid & 31, tid >> 5);
    } else if (b < NB_CVT + NB_T1 + NB_T2) {
        int bb = b - NB_CVT - NB_T1;         // W2: N=512 -> 16 bx, K=1024 -> 32 by
        do_transpose(W2, w2t, D_HID, D_IN, bb & 15, bb >> 4, tid & 31, tid >> 5);
    } else {
        int bb = b - NB_CVT - NB_T1 - NB_T2;
        int i = bb * 256 + tid;
        if (i < N_NODES) cnt[i] = 0;
    }
}

// ---------------------------------------------------------------------------
// Bucketed adjacency fill (4 edges/thread ILP)
// ---------------------------------------------------------------------------
__global__ void fill_kernel(const int* __restrict__ src, const int* __restrict__ dst,
                            int* __restrict__ cnt, int* __restrict__ eidx,
                            int n_edges) {
    int base = (blockIdx.x * blockDim.x + threadIdx.x) * 4;
#pragma unroll
    for (int j = 0; j < 4; j++) {
        int i = base + j;
        if (i < n_edges) {
            int d = dst[i];
            int pos = atomicAdd(&cnt[d], 1);
            eidx[d * CAP + pos] = src[i];
        }
    }
}

// ---------------------------------------------------------------------------
// Fused gather (fp16 feat): one warp per dst node, 4 neighbors in flight.
// rst[d] = (1+eps)*feat[d] + sum feat[s];  f32 accumulate, fp16 out.
// ---------------------------------------------------------------------------
__global__ __launch_bounds__(256)
void gather_kernel(const __half* __restrict__ feath, const float* __restrict__ eps,
                   const int* __restrict__ cnt, const int* __restrict__ eidx,
                   __half* __restrict__ rsth) {
    int node = (blockIdx.x * blockDim.x + threadIdx.x) >> 5;
    int lane = threadIdx.x & 31;
    if (node >= N_NODES) return;

    float acc[16];
    {
        float s = 1.0f + eps[0];
        const uint4* fd = reinterpret_cast<const uint4*>(feath + (size_t)node * D_IN);
#pragma unroll
        for (int i = 0; i < 2; i++) {
            uint4 u = fd[lane + i * 32];
            const __half2* hp = reinterpret_cast<const __half2*>(&u);
#pragma unroll
            for (int q = 0; q < 4; q++) {
                float2 f = __half22float2(hp[q]);
                acc[i * 8 + q * 2 + 0] = s * f.x;
                acc[i * 8 + q * 2 + 1] = s * f.y;
            }
        }
    }
    const int deg = cnt[node];
    const int* ep = eidx + (size_t)node * CAP;
    for (int j0 = 0; j0 < deg; j0 += 32) {
        int mine = (j0 + lane < deg) ? ep[j0 + lane] : 0;
        int m = deg - j0; if (m > 32) m = 32;
        int jj = 0;
        for (; jj + 4 <= m; jj += 4) {
            int s0 = __shfl_sync(0xFFFFFFFFu, mine, jj + 0);
            int s1 = __shfl_sync(0xFFFFFFFFu, mine, jj + 1);
            int s2 = __shfl_sync(0xFFFFFFFFu, mine, jj + 2);
            int s3 = __shfl_sync(0xFFFFFFFFu, mine, jj + 3);
            const uint4* f0 = reinterpret_cast<const uint4*>(feath + (size_t)s0 * D_IN);
            const uint4* f1 = reinterpret_cast<const uint4*>(feath + (size_t)s1 * D_IN);
            const uint4* f2 = reinterpret_cast<const uint4*>(feath + (size_t)s2 * D_IN);
            const uint4* f3 = reinterpret_cast<const uint4*>(feath + (size_t)s3 * D_IN);
            uint4 u0a = f0[lane], u0b = f0[lane + 32];
            uint4 u1a = f1[lane], u1b = f1[lane + 32];
            uint4 u2a = f2[lane], u2b = f2[lane + 32];
            uint4 u3a = f3[lane], u3b = f3[lane + 32];
            acc_u4(acc, u0a); acc_u4(acc + 8, u0b);
            acc_u4(acc, u1a); acc_u4(acc + 8, u1b);
            acc_u4(acc, u2a); acc_u4(acc + 8, u2b);
            acc_u4(acc, u3a); acc_u4(acc + 8, u3b);
        }
        for (; jj < m; jj++) {
            int s = __shfl_sync(0xFFFFFFFFu, mine, jj);
            const uint4* fs = reinterpret_cast<const uint4*>(feath + (size_t)s * D_IN);
            uint4 ua = fs[lane], ub = fs[lane + 32];
            acc_u4(acc, ua); acc_u4(acc + 8, ub);
        }
    }
    uint4* ro = reinterpret_cast<uint4*>(rsth + (size_t)node * D_IN);
#pragma unroll
    for (int i = 0; i < 2; i++) {
        __half2 h0 = __floats2half2_rn(acc[i * 8 + 0], acc[i * 8 + 1]);
        __half2 h1 = __floats2half2_rn(acc[i * 8 + 2], acc[i * 8 + 3]);
        __half2 h2 = __floats2half2_rn(acc[i * 8 + 4], acc[i * 8 + 5]);
        __half2 h3 = __floats2half2_rn(acc[i * 8 + 6], acc[i * 8 + 7]);
        uint4 t;
        t.x = *reinterpret_cast<uint32_t*>(&h0);
        t.y = *reinterpret_cast<uint32_t*>(&h1);
        t.z = *reinterpret_cast<uint32_t*>(&h2);
        t.w = *reinterpret_cast<uint32_t*>(&h3);
        ro[lane + i * 32] = t;
    }
}

// ---------------------------------------------------------------------------
// FP16 mma.sync GEMM (f32 accumulate), 3-stage cp.async pipeline, ldmatrix.
// (unchanged — validated since R10)
// ---------------------------------------------------------------------------
#define TILE_B 16384
#define STAGE_BYTES (2 * TILE_B)
#define NSTAGE 3
#define GSM_TOTAL (NSTAGE * STAGE_BYTES)

template <bool RELU, bool RESID, bool OUT_HALF>
__global__ __launch_bounds__(256, 2)
void gemm_fp16_kernel(const __half* __restrict__ A, const __half* __restrict__ BT,
                      const float* __restrict__ bias, const float* __restrict__ resid,
                      float* __restrict__ Cf, __half* __restrict__ Ch,
                      int M, int N, int K) {
    extern __shared__ char sm[];
    const uint32_t sbase = smem_u32(sm);
    const int tid  = threadIdx.x;
    const int lane = tid & 31;
    const int wid  = tid >> 5;
    const int wm   = wid >> 2;
    const int wn   = wid & 3;
    const int qr   = lane >> 2;
    const int qc   = lane & 3;

    const int rowBase = blockIdx.y * 128;
    const int colBase = blockIdx.x * 128;
    const int NC = K >> 6;

    const int pr = tid >> 3;
    const int pu = tid & 7;

    const int la15  = lane & 15;
    const int ldu   = lane >> 4;
    const int lb_r  = ((lane >> 4) << 3) | (lane & 7);
    const int lb_du = (lane >> 3) & 1;

    float acc[4][4][4];
#pragma unroll
    for (int mf = 0; mf < 4; mf++)
#pragma unroll
        for (int nf = 0; nf < 4; nf++)
#pragma unroll
            for (int r = 0; r < 4; r++) acc[mf][nf][r] = 0.0f;

    auto load_stage = [&](int slot, int chunk) {
        const uint32_t abase = sbase + slot * STAGE_BYTES;
        const uint32_t bbase = abase + TILE_B;
        const int k0 = chunk * 64;
#pragma unroll
        for (int i = 0; i < 4; i++) {
            int r = pr + i * 32;
            int grow = rowBase + r;
            uint32_t dstp = abase + r * 128 + ((pu ^ (r & 7)) << 4);
            const __half* srcp = A + (size_t)grow * K + k0 + pu * 8;
            cp_async16(dstp, srcp, (grow < M) ? 16u : 0u);
        }
#pragma unroll
        for (int i = 0; i < 4; i++) {
            int r = pr + i * 32;
            uint32_t dstp = bbase + r * 128 + ((pu ^ (r & 7)) << 4);
            const __half* srcp = BT + (size_t)(colBase + r) * K + k0 + pu * 8;
            cp_async16(dstp, srcp, 16u);
        }
        CP_COMMIT();
    };

    load_stage(0, 0);
    if (NC > 1) load_stage(1, 1);

    for (int ci = 0; ci < NC; ci++) {
        CP_WAIT1();
        __syncthreads();

        int nci = ci + 2;
        if (nci < NC) load_stage(nci % NSTAGE, nci);

        const int slot = ci % NSTAGE;
        const uint32_t atile = sbase + slot * STAGE_BYTES;
        const uint32_t btile = atile + TILE_B;

#pragma unroll
        for (int ks = 0; ks < 4; ks++) {
            uint32_t a[4][4];
#pragma unroll
            for (int mf = 0; mf < 4; mf++) {
                int r = wm * 64 + mf * 16 + la15;
                uint32_t addr = atile + r * 128 + ((((ks << 1) + ldu) ^ (r & 7)) << 4);
                asm volatile(
                    "ldmatrix.sync.aligned.m8n8.x4.shared.b16 {%0,%1,%2,%3}, [%4];"
                    : "=r"(a[mf][0]), "=r"(a[mf][1]), "=r"(a[mf][2]), "=r"(a[mf][3])
                    : "r"(addr));
            }
            uint32_t b[4][2];
#pragma unroll
            for (int nf2 = 0; nf2 < 2; nf2++) {
                int r = wn * 32 + nf2 * 16 + lb_r;
                uint32_t addr = btile + r * 128 + ((((ks << 1) + lb_du) ^ (r & 7)) << 4);
                asm volatile(
                    "ldmatrix.sync.aligned.m8n8.x4.shared.b16 {%0,%1,%2,%3}, [%4];"
                    : "=r"(b[nf2 * 2][0]), "=r"(b[nf2 * 2][1]),
                      "=r"(b[nf2 * 2 + 1][0]), "=r"(b[nf2 * 2 + 1][1])
                    : "r"(addr));
            }
#pragma unroll
            for (int mf = 0; mf < 4; mf++)
#pragma unroll
                for (int nf = 0; nf < 4; nf++) {
                    asm volatile(
                        "mma.sync.aligned.m16n8k16.row.col.f32.f16.f16.f32 "
                        "{%0,%1,%2,%3}, {%4,%5,%6,%7}, {%8,%9}, {%0,%1,%2,%3};"
                        : "+f"(acc[mf][nf][0]), "+f"(acc[mf][nf][1]),
                          "+f"(acc[mf][nf][2]), "+f"(acc[mf][nf][3])
                        : "r"(a[mf][0]), "r"(a[mf][1]), "r"(a[mf][2]), "r"(a[mf][3]),
                          "r"(b[nf][0]), "r"(b[nf][1]));
                }
        }
        __syncthreads();
    }

#pragma unroll
    for (int mf = 0; mf < 4; mf++) {
#pragma unroll
        for (int half = 0; half < 2; half++) {
            int grow = rowBase + wm * 64 + mf * 16 + qr + half * 8;
            if (grow >= M) continue;
#pragma unroll
            for (int nf = 0; nf < 4; nf++) {
                int gcol = colBase + wn * 32 + nf * 8 + 2 * qc;
                float x = acc[mf][nf][half * 2 + 0] + bias[gcol + 0];
                float y = acc[mf][nf][half * 2 + 1] + bias[gcol + 1];
                if (RELU) { x = fmaxf(x, 0.f); y = fmaxf(y, 0.f); }
                if (RESID) {
                    float2 r = *reinterpret_cast<const float2*>(
                        resid + (size_t)grow * N + gcol);
                    x += r.x; y += r.y;
                }
                if (OUT_HALF) {
                    __half2 hv = __floats2half2_rn(x, y);
                    *reinterpret_cast<uint32_t*>(Ch + (size_t)grow * N + gcol) =
                        *reinterpret_cast<uint32_t*>(&hv);
                } else {
                    float2 v; v.x = x; v.y = y;
                    *reinterpret_cast<float2*>(Cf + (size_t)grow * N + gcol) = v;
                }
            }
        }
    }
}

// ---------------------------------------------------------------------------
extern "C" void kernel_launch(void* const* d_in, const int* in_sizes, int n_in,
                              void* d_out, int out_size) {
    const float* feat = (const float*)d_in[0];
    const float* W1   = (const float*)d_in[1];
    const float* b1   = (const float*)d_in[2];
    const float* W2   = (const float*)d_in[3];
    const float* b2   = (const float*)d_in[4];
    const float* eps  = (const float*)d_in[5];
    const int*   src  = (const int*)d_in[6];
    const int*   dst  = (const int*)d_in[7];
    const int n_edges = in_sizes[6];
    float* out = (float*)d_out;

    __half *feath = nullptr, *rsth = nullptr, *h = nullptr, *w1t = nullptr, *w2t = nullptr;
    int *cnt = nullptr, *eidx = nullptr;
    cudaGetSymbolAddress((void**)&feath, g_feat_h);
    cudaGetSymbolAddress((void**)&rsth, g_rst_h);
    cudaGetSymbolAddress((void**)&h, g_h);
    cudaGetSymbolAddress((void**)&w1t, g_w1t);
    cudaGetSymbolAddress((void**)&w2t, g_w2t);
    cudaGetSymbolAddress((void**)&cnt, g_cnt);
    cudaGetSymbolAddress((void**)&eidx, g_eidx);

    cudaFuncSetAttribute(gemm_fp16_kernel<true, false, true>,
                         cudaFuncAttributeMaxDynamicSharedMemorySize, GSM_TOTAL);
    cudaFuncSetAttribute(gemm_fp16_kernel<false, true, false>,
                         cudaFuncAttributeMaxDynamicSharedMemorySize, GSM_TOTAL);

    // 1) fused prep: feat->fp16, W1/W2 transpose+cvt, zero cnt
    prep_kernel<<<NB_PREP, 256>>>(feat, W1, W2, feath, w1t, w2t, cnt);
    // 2) adjacency fill
    {
        int threads_needed = (n_edges + 3) / 4;
        fill_kernel<<<(threads_needed + 255) / 256, 256>>>(src, dst, cnt, eidx, n_edges);
    }
    // 3) fused gather (fp16 feat) -> fp16 rst
    {
        int blocks = (N_NODES + 7) / 8;
        gather_kernel<<<blocks, 256>>>(feath, eps, cnt, eidx, rsth);
    }
    // 4) h = fp16(relu(rst @ W1 + b1))
    {
        dim3 grid(D_HID / 128, (N_NODES + 127) / 128);
        gemm_fp16_kernel<true, false, true><<<grid, 256, GSM_TOTAL>>>(
            rsth, w1t, b1, nullptr, nullptr, h, N_NODES, D_HID, D_IN);
    }
    // 5) out = h @ W2 + b2 + feat
    {
        dim3 grid(D_IN / 128, (N_NODES + 127) / 128);
        gemm_fp16_kernel<false, true, false><<<grid, 256, GSM_TOTAL>>>(
            h, w2t, b2, feat, out, nullptr, N_NODES, D_IN, D_HID);
    }
}